// round 5
// baseline (speedup 1.0000x reference)
#include <cuda_runtime.h>
#include <math.h>

// ============================================================================
// Model_90168543412725 — graph attention Q network
// B=16, R=8, C=1023 cities, N=1024 nodes, H=64, T1=T2=5
//
// Restructure: sigmoid(d*w) with |d*w|<=1 replaced by odd Taylor poly deg 7:
//   sigma(x) ~= a0 + a1 x + a3 x^3 + a5 x^5 + a7 x^7   (|err| <= 1.1e-5)
// =>  l[b,i,h] = sum_{k,c} (P[b,i,c] d[b,i,c]^k) * (a_k w_h^k u[b,c,h])
// i.e. one GEMM per iteration with K = 5*1023 = 5115. A-matrix (Pk) is
// iteration- and phase-independent (shared T1/T2); B-matrix is tiny, rebuilt
// per iteration from u/gamma.
// ============================================================================

#define NB 16
#define CC 1023
#define NN 1024
#define GK 5115            // 5 * 1023
#define PS ((size_t)1023*1024)   // Pk plane stride per power index

// ---- scratch (device globals; no runtime allocation) ----
__device__ __align__(16) float g_Pk[16*5*1023*1024];  // [b][k][c][i]  335 MB
__device__ __align__(16) float g_Bt[16*5115*128];     // [b][kappa][h] 42 MB
__device__ __align__(16) float g_L [16*1024*128];     // l output of GEMM
__device__ __align__(16) float g_U [16*1024*64];      // u_a
__device__ __align__(16) float g_UC[16*1024*128];     // [u_a, u_b]
__device__ __align__(16) float g_X2[16*1024*128];     // u_concat @ W_x_2
__device__ __align__(16) float g_G [16*1024*128];     // gamma
__device__ float g_xa[16*1024];
__device__ float g_wp1[5*64];                          // a_k * w1a^pow(k)
__device__ float g_wp2[5*128];                         // a_k * w2 ^pow(k)

// ---------------------------------------------------------------------------
// x_a[b,n] = max_r x_a_state[b,r,n] * (assignment_prev + action)[b,r,n]
// ---------------------------------------------------------------------------
__global__ void xa_kernel(const float* __restrict__ xs,
                          const float* __restrict__ ap,
                          const float* __restrict__ act) {
    int idx = blockIdx.x * 256 + threadIdx.x;   // b*1024 + n
    if (idx >= NB * NN) return;
    int b = idx >> 10, n = idx & 1023;
    float mx = -3.4e38f;
#pragma unroll
    for (int r = 0; r < 8; r++) {
        int o = (b * 8 + r) * NN + n;
        mx = fmaxf(mx, xs[o] * (ap[o] + act[o]));
    }
    g_xa[idx] = mx;
}

// ---------------------------------------------------------------------------
// wp[k][h] = a_k * w_h^pow(k),  pow = {0,1,3,5,7}
// ---------------------------------------------------------------------------
__global__ void wpow_kernel(const float* __restrict__ w1a,
                            const float* __restrict__ w2) {
    const float a0 = 0.5f, a1 = 0.25f, a3 = -1.f/48.f,
                a5 = 1.f/480.f, a7 = -17.f/80640.f;
    int h = threadIdx.x;
    if (h < 64) {
        float w = w1a[h]; float ww = w * w;
        float w3 = w * ww, w5 = w3 * ww, w7 = w5 * ww;
        g_wp1[0*64+h] = a0;     g_wp1[1*64+h] = a1*w;
        g_wp1[2*64+h] = a3*w3;  g_wp1[3*64+h] = a5*w5;
        g_wp1[4*64+h] = a7*w7;
    }
    if (h < 128) {
        float w = w2[h]; float ww = w * w;
        float w3 = w * ww, w5 = w3 * ww, w7 = w5 * ww;
        g_wp2[0*128+h] = a0;    g_wp2[1*128+h] = a1*w;
        g_wp2[2*128+h] = a3*w3; g_wp2[3*128+h] = a5*w5;
        g_wp2[4*128+h] = a7*w7;
    }
}

// ---------------------------------------------------------------------------
// Presence attention + Pk build.  One block per (b,c).
// h1 = relu(edge @ W1), h2 = relu(h1 @ W2); masked softmax over n;
// Pk[b][k][c][n] = prob(n) * d(n)^pow(k),  d = edge[b,c,n,0]
// ---------------------------------------------------------------------------
__global__ __launch_bounds__(256) void presence_kernel(
        const float* __restrict__ edge, const float* __restrict__ avail,
        const float* __restrict__ W1, const float* __restrict__ W2) {
    const int c = blockIdx.x;     // 0..1022
    const int b = blockIdx.y;
    __shared__ __align__(16) float4 w4[64];
    __shared__ float lbuf[1024];
    __shared__ float dbuf[1024];
    __shared__ float red[256];
    int tid = threadIdx.x;
    if (tid < 64) w4[tid] = make_float4(W1[tid], W1[64+tid], W1[128+tid], W2[tid]);
    __syncthreads();

    for (int n = tid; n < NN; n += 256) {
        size_t base = ((size_t)(b * CC + c) * NN + n) * 3;
        float e0 = edge[base], e1 = edge[base+1], e2 = edge[base+2];
        float s = 0.f;
#pragma unroll 16
        for (int j = 0; j < 64; j++) {
            float4 w = w4[j];
            float h = fmaf(e0, w.x, fmaf(e1, w.y, e2 * w.z));
            h = fmaxf(h, 0.f);
            s = fmaf(h, w.w, s);
        }
        float h2 = fmaxf(s, 0.f);                   // TAU = 1
        float m = (n == c ? 0.f : 1.f) * avail[b * NN + n];
        lbuf[n] = h2 * m - (1.f - m) * 1e10f;
        dbuf[n] = e0;
    }
    __syncthreads();

    // block max
    float mx = -3.4e38f;
    for (int n = tid; n < NN; n += 256) mx = fmaxf(mx, lbuf[n]);
    red[tid] = mx; __syncthreads();
    for (int k = 128; k > 0; k >>= 1) {
        if (tid < k) red[tid] = fmaxf(red[tid], red[tid + k]);
        __syncthreads();
    }
    mx = red[0];

    float sm = 0.f;
    for (int n = tid; n < NN; n += 256) {
        float e = __expf(lbuf[n] - mx);
        lbuf[n] = e; sm += e;
    }
    __syncthreads();
    red[tid] = sm; __syncthreads();
    for (int k = 128; k > 0; k >>= 1) {
        if (tid < k) red[tid] += red[tid + k];
        __syncthreads();
    }
    float inv = 1.f / red[0];

    for (int n = tid; n < NN; n += 256) {
        float p = lbuf[n] * inv;
        float d = dbuf[n];
        float d2 = d * d;
        size_t i0 = ((size_t)(b * 5) * CC + c) * NN + n;
        g_Pk[i0]        = p;
        float q = p * d; g_Pk[i0 + PS]   = q;
        q *= d2;         g_Pk[i0 + 2*PS] = q;
        q *= d2;         g_Pk[i0 + 3*PS] = q;
        q *= d2;         g_Pk[i0 + 4*PS] = q;
    }
}

// ---------------------------------------------------------------------------
// Bt[b][kappa=(k,c)][h] = wp[k][h] * U[b][c][h]
// sel: 0 -> ext (input tensor), 1 -> g_U, 2 -> g_G.   blockDim.x == NH.
// ---------------------------------------------------------------------------
__global__ void buildB_kernel(int sel, const float* __restrict__ ext, int NH) {
    int kap = blockIdx.x;               // 0..5114
    int b = blockIdx.y;
    int h = threadIdx.x;
    int kk = kap / 1023;
    int c  = kap - kk * 1023;
    const float* wp = (NH == 64) ? g_wp1 : g_wp2;
    const float* U  = (sel == 0) ? ext : (sel == 1 ? g_U : g_G);
    float v = wp[kk * NH + h] * U[((size_t)b * NN + c) * NH + h];
    g_Bt[((size_t)b * GK + kap) * NH + h] = v;
}

// ---------------------------------------------------------------------------
// GEMM (TN over extended-K):  L[b][i][h] = sum_kappa Pk[b][kappa][i] * Bt[b][kappa][h]
// Tile 128(M) x 64(N) x 16(K), 256 threads, 8x4 register tile.
// ---------------------------------------------------------------------------
__global__ __launch_bounds__(256) void gemm_tn_kernel(int NH) {
    const int b  = blockIdx.z;
    const int m0 = blockIdx.x * 128;
    const int n0 = blockIdx.y * 64;
    const float* A  = g_Pk + (size_t)b * GK * NN;
    const float* Bm = g_Bt + (size_t)b * GK * NH;
    float*       Cm = g_L  + (size_t)b * NN * NH;

    __shared__ __align__(16) float As[16 * 128];
    __shared__ __align__(16) float Bs[16 * 64];

    const int tid = threadIdx.x;
    const int tx = tid & 15, ty = tid >> 4;
    const int mb = ty * 8, nb = tx * 4;

    const int arow = tid >> 5;            // 0..7
    const int acol = (tid & 31) * 4;      // 0..124
    const int brow = tid >> 4;            // 0..15
    const int bcol = (tid & 15) * 4;      // 0..60

    float acc[8][4];
#pragma unroll
    for (int i = 0; i < 8; i++)
#pragma unroll
        for (int j = 0; j < 4; j++) acc[i][j] = 0.f;

    for (int k0 = 0; k0 < GK; k0 += 16) {
#pragma unroll
        for (int r = 0; r < 2; r++) {
            int kr = arow + r * 8;
            int kg = k0 + kr;
            float4 v = make_float4(0.f, 0.f, 0.f, 0.f);
            if (kg < GK) v = *(const float4*)(A + (size_t)kg * NN + m0 + acol);
            *(float4*)(As + kr * 128 + acol) = v;
        }
        {
            int kg = k0 + brow;
            float4 v = make_float4(0.f, 0.f, 0.f, 0.f);
            if (kg < GK) v = *(const float4*)(Bm + (size_t)kg * NH + n0 + bcol);
            *(float4*)(Bs + brow * 64 + bcol) = v;
        }
        __syncthreads();
#pragma unroll
        for (int kk = 0; kk < 16; kk++) {
            float4 b4 = *(const float4*)(Bs + kk * 64 + nb);
            float4 a0 = *(const float4*)(As + kk * 128 + mb);
            float4 a1 = *(const float4*)(As + kk * 128 + mb + 4);
            float av[8] = {a0.x, a0.y, a0.z, a0.w, a1.x, a1.y, a1.z, a1.w};
            float bv[4] = {b4.x, b4.y, b4.z, b4.w};
#pragma unroll
            for (int i = 0; i < 8; i++)
#pragma unroll
                for (int j = 0; j < 4; j++)
                    acc[i][j] = fmaf(av[i], bv[j], acc[i][j]);
        }
        __syncthreads();
    }
#pragma unroll
    for (int i = 0; i < 8; i++) {
        int m = m0 + mb + i;
        *(float4*)(Cm + (size_t)m * NH + n0 + nb) =
            make_float4(acc[i][0], acc[i][1], acc[i][2], acc[i][3]);
    }
}

// ---------------------------------------------------------------------------
// T1 update: out = relu(L @ Wl + xa * wx)
// dest: 0 -> g_U ; 1 -> g_UC[:, :64] ; 2 -> g_UC[:, 64:]
// block handles 8 i's; grid(128, 16)
// ---------------------------------------------------------------------------
__global__ __launch_bounds__(256) void update1_kernel(
        const float* __restrict__ Wl, const float* __restrict__ wx, int dest) {
    int b = blockIdx.y;
    int i0 = blockIdx.x * 8;
    __shared__ __align__(16) float Ls[8 * 64];
    int tid = threadIdx.x;
    for (int t = tid; t < 512; t += 256)
        Ls[t] = g_L[((size_t)b * NN + i0) * 64 + t];
    __syncthreads();
    int h = tid & 63, iq = tid >> 6;
    float a0 = 0.f, a1 = 0.f;
#pragma unroll 8
    for (int hp = 0; hp < 64; hp++) {
        float wv = Wl[hp * 64 + h];
        a0 = fmaf(Ls[iq * 64 + hp],       wv, a0);
        a1 = fmaf(Ls[(iq + 4) * 64 + hp], wv, a1);
    }
    float wxh = wx[h];
    int i1 = i0 + iq, i2 = i0 + iq + 4;
    float v1 = fmaxf(a0 + g_xa[b * NN + i1] * wxh, 0.f);
    float v2 = fmaxf(a1 + g_xa[b * NN + i2] * wxh, 0.f);
    if (dest == 0) {
        g_U[((size_t)b * NN + i1) * 64 + h] = v1;
        g_U[((size_t)b * NN + i2) * 64 + h] = v2;
    } else {
        int off = (dest == 1) ? 0 : 64;
        g_UC[((size_t)b * NN + i1) * 128 + off + h] = v1;
        g_UC[((size_t)b * NN + i2) * 128 + off + h] = v2;
    }
}

// ---------------------------------------------------------------------------
// 128-wide dense.  mode 0: g_X2 = g_UC @ W (no bias/relu)
//                  mode 1: g_G  = relu(g_L @ W + g_X2)
// block handles 8 i's; grid(128,16)
// ---------------------------------------------------------------------------
__global__ __launch_bounds__(256) void dense128_kernel(
        const float* __restrict__ W, int mode) {
    int b = blockIdx.y;
    int i0 = blockIdx.x * 8;
    __shared__ __align__(16) float Ls[8 * 128];
    const float* In = (mode == 0) ? g_UC : g_L;
    int tid = threadIdx.x;
    for (int t = tid; t < 1024; t += 256)
        Ls[t] = In[((size_t)b * NN + i0) * 128 + t];
    __syncthreads();
    int h = tid & 127, iq = tid >> 7;
    float a[4] = {0.f, 0.f, 0.f, 0.f};
#pragma unroll 8
    for (int hp = 0; hp < 128; hp++) {
        float wv = W[hp * 128 + h];
#pragma unroll
        for (int u = 0; u < 4; u++)
            a[u] = fmaf(Ls[(iq + 2 * u) * 128 + hp], wv, a[u]);
    }
#pragma unroll
    for (int u = 0; u < 4; u++) {
        int i = i0 + iq + 2 * u;
        size_t o = ((size_t)b * NN + i) * 128 + h;
        if (mode == 1) g_G[o] = fmaxf(a[u] + g_X2[o], 0.f);
        else           g_X2[o] = a[u];
    }
}

// ---------------------------------------------------------------------------
// Q[b] = sum_{i,h} gamma[b,i,h] * WQ[h]
// ---------------------------------------------------------------------------
__global__ void qreduce_kernel(const float* __restrict__ WQ, float* __restrict__ out) {
    int b = blockIdx.x;
    int tid = threadIdx.x;
    const float* G = g_G + (size_t)b * NN * 128;
    float s = 0.f;
    for (int idx = tid; idx < NN * 128; idx += 256) {
        int h = idx & 127;
        s = fmaf(G[idx], WQ[h], s);
    }
    __shared__ float red[256];
    red[tid] = s; __syncthreads();
    for (int k = 128; k > 0; k >>= 1) {
        if (tid < k) red[tid] += red[tid + k];
        __syncthreads();
    }
    if (tid == 0) out[b] = red[0];
}

// ---------------------------------------------------------------------------
extern "C" void kernel_launch(void* const* d_in, const int* in_sizes, int n_in,
                              void* d_out, int out_size) {
    (void)in_sizes; (void)n_in; (void)out_size;
    const float* x_a_state = (const float*)d_in[0];
    const float* assign_pr = (const float*)d_in[1];
    const float* action    = (const float*)d_in[2];
    const float* edge      = (const float*)d_in[3];
    const float* avail     = (const float*)d_in[4];
    const float* u_a0      = (const float*)d_in[5];
    // d_in[6] = u_b0 : unused (dead in reference)
    const float* gamma0    = (const float*)d_in[7];
    const float* W1p       = (const float*)d_in[8];
    const float* W2p       = (const float*)d_in[9];
    const float* W_x_1a    = (const float*)d_in[10];
    const float* W_emb_1a  = (const float*)d_in[11];
    const float* W_l_1a    = (const float*)d_in[12];
    const float* W_x_1b    = (const float*)d_in[13];
    // d_in[14] = W_emb_1b : unused (l_a reuse bug in reference)
    const float* W_l_1b    = (const float*)d_in[15];
    const float* W_x_2     = (const float*)d_in[16];
    const float* W_emb_2   = (const float*)d_in[17];
    const float* W_l_2     = (const float*)d_in[18];
    const float* W_Q       = (const float*)d_in[19];
    float* outp = (float*)d_out;

    xa_kernel<<<(NB * NN + 255) / 256, 256>>>(x_a_state, assign_pr, action);
    wpow_kernel<<<1, 128>>>(W_emb_1a, W_emb_2);
    presence_kernel<<<dim3(CC, NB), 256>>>(edge, avail, W1p, W2p);

    // ---- T1: u_a iterations (u_b only needs final l_a) ----
    for (int t = 0; t < 5; t++) {
        buildB_kernel<<<dim3(GK, NB), 64>>>(t == 0 ? 0 : 1, u_a0, 64);
        gemm_tn_kernel<<<dim3(8, 1, NB), 256>>>(64);
        if (t < 4) {
            update1_kernel<<<dim3(128, NB), 256>>>(W_l_1a, W_x_1a, 0);
        } else {
            update1_kernel<<<dim3(128, NB), 256>>>(W_l_1a, W_x_1a, 1);  // u_a -> UC[:, :64]
            update1_kernel<<<dim3(128, NB), 256>>>(W_l_1b, W_x_1b, 2);  // u_b -> UC[:, 64:]
        }
    }

    // x2 = u_concat @ W_x_2
    dense128_kernel<<<dim3(128, NB), 256>>>(W_x_2, 0);

    // ---- T2: gamma iterations ----
    for (int t = 0; t < 5; t++) {
        buildB_kernel<<<dim3(GK, NB), 128>>>(t == 0 ? 0 : 2, gamma0, 128);
        gemm_tn_kernel<<<dim3(8, 2, NB), 256>>>(128);
        dense128_kernel<<<dim3(128, NB), 256>>>(W_l_2, 1);
    }

    qreduce_kernel<<<NB, 256>>>(W_Q, outp);
}

// round 10
// speedup vs baseline: 4.5771x; 4.5771x over previous
#include <cuda_runtime.h>
#include <cuda_fp16.h>
#include <math.h>
#include <stdint.h>

// ============================================================================
// Model_90168543412725 — graph attention Q network
// B=16, C=1023 cities, N=1024 nodes, H=64, T1=T2=5
//
// sigmoid(d*w), |d*w|<=1 -> deg-7 odd Taylor -> per-iteration GEMM with
// K = 5*1023 (padded 5120):
//   l[b,i,h] = sum_{k,c} (P[b,i,c] d^k) * (a_k w_h^k u[b,c,h])
// Engine: mma.sync.m16n8k16 FP16 (bf16 was 2e-3 rel err -> over threshold;
// fp16's 10 mantissa bits give ~2.5e-4). fp32 accumulate.
// ============================================================================

#define NB 16
#define CC 1023
#define NN 1024
#define KPAD 5120
#define KCH 64
#define NCHUNK (KPAD / KCH)            // 80
#define PSE ((size_t)CC * NN)

// ---- scratch (device globals; .bss zero-init — K-pad rows stay zero) ----
__device__ __align__(16) __half g_Pk [(size_t)NB * KPAD * NN];   // [b][kappa][i]
__device__ __align__(16) __half g_Bt1[(size_t)NB * 128 * KPAD];  // [b][h][kappa]
__device__ __align__(16) __half g_Bt2[(size_t)NB * 128 * KPAD];
__device__ __align__(16) float g_L [NB * NN * 128];
__device__ __align__(16) float g_U [NB * NN * 64];
__device__ __align__(16) float g_UC[NB * NN * 128];
__device__ __align__(16) float g_X2[NB * NN * 128];
__device__ __align__(16) float g_G [NB * NN * 128];
__device__ float g_xa[NB * NN];
__device__ float g_wp1[5 * 64];
__device__ float g_wp2[5 * 128];

// ---------------------------------------------------------------------------
__device__ __forceinline__ uint32_t s2u(const void* p) {
    uint32_t a;
    asm("{ .reg .u64 t; cvta.to.shared.u64 t, %1; cvt.u32.u64 %0, t; }"
        : "=r"(a) : "l"(p));
    return a;
}
#define SWZ(x) ((x) ^ (((x) >> 3) & 0x70))

#define LDSM_X4(r, addr)                                                      \
    asm volatile("ldmatrix.sync.aligned.m8n8.x4.shared.b16 {%0,%1,%2,%3}, [%4];" \
        : "=r"((r)[0]), "=r"((r)[1]), "=r"((r)[2]), "=r"((r)[3]) : "r"(addr))
#define LDSM_X2T(r, addr)                                                     \
    asm volatile("ldmatrix.sync.aligned.m8n8.x2.trans.shared.b16 {%0,%1}, [%2];" \
        : "=r"((r)[0]), "=r"((r)[1]) : "r"(addr))
#define MMA16816(d, a, bb)                                                    \
    asm volatile(                                                             \
        "mma.sync.aligned.m16n8k16.row.col.f32.f16.f16.f32 "                  \
        "{%0,%1,%2,%3}, {%4,%5,%6,%7}, {%8,%9}, {%0,%1,%2,%3};"               \
        : "+f"((d)[0]), "+f"((d)[1]), "+f"((d)[2]), "+f"((d)[3])              \
        : "r"((a)[0]), "r"((a)[1]), "r"((a)[2]), "r"((a)[3]),                 \
          "r"((bb)[0]), "r"((bb)[1]))
#define CP_ASYNC16(s, g)                                                      \
    asm volatile("cp.async.cg.shared.global [%0], [%1], 16;"                  \
        :: "r"(s), "l"(g) : "memory")
#define CP_COMMIT() asm volatile("cp.async.commit_group;" ::: "memory")
#define CP_WAIT(n)  asm volatile("cp.async.wait_group %0;" :: "n"(n) : "memory")

// ---------------------------------------------------------------------------
// x_a[b,n] = max_r x_a_state[b,r,n] * (assignment_prev + action)[b,r,n]
// ---------------------------------------------------------------------------
__global__ void xa_kernel(const float* __restrict__ xs,
                          const float* __restrict__ ap,
                          const float* __restrict__ act) {
    int idx = blockIdx.x * 256 + threadIdx.x;
    if (idx >= NB * NN) return;
    int b = idx >> 10, n = idx & 1023;
    float mx = -3.4e38f;
#pragma unroll
    for (int r = 0; r < 8; r++) {
        int o = (b * 8 + r) * NN + n;
        mx = fmaxf(mx, xs[o] * (ap[o] + act[o]));
    }
    g_xa[idx] = mx;
}

// ---------------------------------------------------------------------------
// wp[k][h] = a_k * w_h^pow(k),  pow = {0,1,3,5,7}
// ---------------------------------------------------------------------------
__global__ void wpow_kernel(const float* __restrict__ w1a,
                            const float* __restrict__ w2) {
    const float a0 = 0.5f, a1 = 0.25f, a3 = -1.f/48.f,
                a5 = 1.f/480.f, a7 = -17.f/80640.f;
    int h = threadIdx.x;
    if (h < 64) {
        float w = w1a[h]; float ww = w * w;
        float w3 = w * ww, w5 = w3 * ww, w7 = w5 * ww;
        g_wp1[0*64+h] = a0;     g_wp1[1*64+h] = a1*w;
        g_wp1[2*64+h] = a3*w3;  g_wp1[3*64+h] = a5*w5;
        g_wp1[4*64+h] = a7*w7;
    }
    if (h < 128) {
        float w = w2[h]; float ww = w * w;
        float w3 = w * ww, w5 = w3 * ww, w7 = w5 * ww;
        g_wp2[0*128+h] = a0;    g_wp2[1*128+h] = a1*w;
        g_wp2[2*128+h] = a3*w3; g_wp2[3*128+h] = a5*w5;
        g_wp2[4*128+h] = a7*w7;
    }
}

// ---------------------------------------------------------------------------
// Presence attention + Pk build (fp16). One block per (b,c).
// Pk[b][k*1023+c][n] = softmax_n(logit)[n] * d(n)^pow(k)
// ---------------------------------------------------------------------------
__global__ __launch_bounds__(256) void presence_kernel(
        const float* __restrict__ edge, const float* __restrict__ avail,
        const float* __restrict__ W1, const float* __restrict__ W2) {
    const int c = blockIdx.x;
    const int b = blockIdx.y;
    __shared__ __align__(16) float4 w4[64];
    __shared__ float lbuf[1024];
    __shared__ float dbuf[1024];
    __shared__ float red[256];
    int tid = threadIdx.x;
    if (tid < 64) w4[tid] = make_float4(W1[tid], W1[64+tid], W1[128+tid], W2[tid]);
    __syncthreads();

    for (int n = tid; n < NN; n += 256) {
        size_t base = ((size_t)(b * CC + c) * NN + n) * 3;
        float e0 = edge[base], e1 = edge[base+1], e2 = edge[base+2];
        float s = 0.f;
#pragma unroll 16
        for (int j = 0; j < 64; j++) {
            float4 w = w4[j];
            float h = fmaf(e0, w.x, fmaf(e1, w.y, e2 * w.z));
            h = fmaxf(h, 0.f);
            s = fmaf(h, w.w, s);
        }
        float h2 = fmaxf(s, 0.f);
        float m = (n == c ? 0.f : 1.f) * avail[b * NN + n];
        lbuf[n] = h2 * m - (1.f - m) * 1e10f;
        dbuf[n] = e0;
    }
    __syncthreads();

    float mx = -3.4e38f;
    for (int n = tid; n < NN; n += 256) mx = fmaxf(mx, lbuf[n]);
    red[tid] = mx; __syncthreads();
    for (int k = 128; k > 0; k >>= 1) {
        if (tid < k) red[tid] = fmaxf(red[tid], red[tid + k]);
        __syncthreads();
    }
    mx = red[0];

    float sm = 0.f;
    for (int n = tid; n < NN; n += 256) {
        float e = __expf(lbuf[n] - mx);
        lbuf[n] = e; sm += e;
    }
    __syncthreads();
    red[tid] = sm; __syncthreads();
    for (int k = 128; k > 0; k >>= 1) {
        if (tid < k) red[tid] += red[tid + k];
        __syncthreads();
    }
    float inv = 1.f / red[0];

    for (int n = tid; n < NN; n += 256) {
        float p = lbuf[n] * inv;
        float d = dbuf[n];
        float d2 = d * d;
        size_t i0 = ((size_t)b * KPAD + c) * NN + n;
        g_Pk[i0]           = __float2half(p);
        float q = p * d;  g_Pk[i0 + PSE]     = __float2half(q);
        q *= d2;          g_Pk[i0 + 2 * PSE] = __float2half(q);
        q *= d2;          g_Pk[i0 + 3 * PSE] = __float2half(q);
        q *= d2;          g_Pk[i0 + 4 * PSE] = __float2half(q);
    }
}

// ---------------------------------------------------------------------------
// buildB (transpose): Bt[b][h][k*1023+c] = wp[k][h] * U[b][c][h]  (fp16)
// sel: 0 -> ext, 1 -> g_U, 2 -> g_G.  phase: 0 -> Bt1, 1 -> Bt2.
// ---------------------------------------------------------------------------
__global__ __launch_bounds__(256) void buildB_kernel(int sel, const float* __restrict__ ext,
                                                     int NH, int phase) {
    int b = blockIdx.y, c0 = blockIdx.x * 64;
    __shared__ float Us[64 * 129];
    const int stride = NH + 1;
    const float* U = (sel == 0) ? ext : (sel == 1 ? g_U : g_G);
    const float* wp = (NH == 64) ? g_wp1 : g_wp2;
    __half* Bt = phase ? g_Bt2 : g_Bt1;
    int tid = threadIdx.x;
    for (int idx = tid; idx < 64 * NH; idx += 256) {
        int cl = idx / NH, h = idx - cl * NH;
        Us[cl * stride + h] = U[((size_t)b * NN + c0 + cl) * NH + h];
    }
    __syncthreads();
    int w = tid >> 5, l = tid & 31;
    for (int r = w; r < NH * 5; r += 8) {
        int k = r / NH;
        int h = r - k * NH;
        float s = wp[k * NH + h];
        size_t base = ((size_t)b * 128 + h) * KPAD + k * 1023 + c0;
        if (c0 + l < CC)
            Bt[base + l] = __float2half(s * Us[l * stride + h]);
        if (c0 + l + 32 < CC)
            Bt[base + l + 32] = __float2half(s * Us[(l + 32) * stride + h]);
    }
}

// ---------------------------------------------------------------------------
// fp16 GEMM via mma.sync m16n8k16:
//   L[b][i][h] = sum_kappa Bt[b][h][kappa] * Pk[b][kappa][i]
// D[m=h(NH)][n=i(64)]. A (Bt) row-major over kappa -> ldmatrix.x4.
// B (Pk) [kappa][i] -> ldmatrix.x2.trans gives the col-major B fragment.
// SW128 XOR swizzle on both smem tiles; 2-stage cp.async pipeline.
// grid (16 i-tiles, NB), 256 threads / 8 warps.
// ---------------------------------------------------------------------------
template<int NH>
__global__ void __launch_bounds__(256) gemm_kernel() {
    constexpr int ASZ = NH * 128;      // bytes per A stage (NH rows x 128B)
    constexpr int BSZ = 64 * 128;      // 8 KB per B stage
    constexpr int WN  = (NH == 128) ? 2 : 4;   // n-warps
    constexpr int NTI = (NH == 128) ? 4 : 2;   // n8 tiles per warp
    __shared__ __align__(128) char smem[2 * (ASZ + BSZ)];

    const int b = blockIdx.y;
    const int i0 = blockIdx.x * 64;
    const __half* Ag = (NH == 64 ? g_Bt1 : g_Bt2) + (size_t)b * 128 * KPAD;
    const __half* Bg = g_Pk + (size_t)b * KPAD * NN + i0;

    const int tid = threadIdx.x, lane = tid & 31, wid = tid >> 5;
    const int wm = wid / WN, wn = wid % WN;
    const uint32_t sb = s2u(smem);

    float acc[2][NTI][4];
#pragma unroll
    for (int mi = 0; mi < 2; mi++)
#pragma unroll
        for (int ni = 0; ni < NTI; ni++)
#pragma unroll
            for (int q = 0; q < 4; q++) acc[mi][ni][q] = 0.f;

    const int gr = tid >> 3;           // 0..31
    const int gc = (tid & 7) * 16;     // byte col

    // ---- stage-0 prefetch ----
    {
        size_t k0 = 0;
#pragma unroll
        for (int p = 0; p < ASZ / (256 * 16); p++) {
            int r = p * 32 + gr;
            CP_ASYNC16(sb + SWZ(r * 128 + gc),
                       (const char*)(Ag + (size_t)r * KPAD + k0) + gc);
        }
#pragma unroll
        for (int p = 0; p < 2; p++) {
            int r = p * 32 + gr;
            CP_ASYNC16(sb + 2 * ASZ + SWZ(r * 128 + gc),
                       (const char*)(Bg + (k0 + r) * NN) + gc);
        }
        CP_COMMIT();
    }

    for (int ch = 0; ch < NCHUNK; ch++) {
        if (ch + 1 < NCHUNK) {
            int buf = (ch + 1) & 1;
            size_t k0 = (size_t)(ch + 1) * KCH;
#pragma unroll
            for (int p = 0; p < ASZ / (256 * 16); p++) {
                int r = p * 32 + gr;
                CP_ASYNC16(sb + buf * ASZ + SWZ(r * 128 + gc),
                           (const char*)(Ag + (size_t)r * KPAD + k0) + gc);
            }
#pragma unroll
            for (int p = 0; p < 2; p++) {
                int r = p * 32 + gr;
                CP_ASYNC16(sb + 2 * ASZ + buf * BSZ + SWZ(r * 128 + gc),
                           (const char*)(Bg + (k0 + r) * NN) + gc);
            }
            CP_COMMIT();
            CP_WAIT(1);
        } else {
            CP_WAIT(0);
        }
        __syncthreads();

        const uint32_t Ab = sb + (ch & 1) * ASZ;
        const uint32_t Bb = sb + 2 * ASZ + (ch & 1) * BSZ;
#pragma unroll
        for (int kk = 0; kk < 4; kk++) {
            uint32_t af[2][4];
#pragma unroll
            for (int mi = 0; mi < 2; mi++) {
                int r = wm * 32 + mi * 16 + (lane & 15);
                int c = kk * 16 + ((lane >> 4) << 3);
                LDSM_X4(af[mi], Ab + SWZ(r * 128 + c * 2));
            }
            uint32_t bf[NTI][2];
#pragma unroll
            for (int ni = 0; ni < NTI; ni++) {
                int r = kk * 16 + (lane & 15);
                int c = wn * (NTI * 8) + ni * 8;
                LDSM_X2T(bf[ni], Bb + SWZ(r * 128 + c * 2));
            }
#pragma unroll
            for (int mi = 0; mi < 2; mi++)
#pragma unroll
                for (int ni = 0; ni < NTI; ni++)
                    MMA16816(acc[mi][ni], af[mi], bf[ni]);
        }
        __syncthreads();
    }

    // ---- epilogue: L[b][i][h] ----
    float* Lp = g_L + ((size_t)b * NN + i0) * NH;
    const int g = lane >> 2, tg = lane & 3;
#pragma unroll
    for (int mi = 0; mi < 2; mi++) {
        int h0 = wm * 32 + mi * 16 + g;
#pragma unroll
        for (int ni = 0; ni < NTI; ni++) {
            int ic = wn * (NTI * 8) + ni * 8 + tg * 2;
            Lp[(size_t)ic * NH + h0]            = acc[mi][ni][0];
            Lp[(size_t)(ic + 1) * NH + h0]      = acc[mi][ni][1];
            Lp[(size_t)ic * NH + h0 + 8]        = acc[mi][ni][2];
            Lp[(size_t)(ic + 1) * NH + h0 + 8]  = acc[mi][ni][3];
        }
    }
}

// ---------------------------------------------------------------------------
// T1 update: out = relu(L @ Wl + xa * wx);  dest 0 -> g_U, 1/2 -> g_UC halves
// ---------------------------------------------------------------------------
__global__ __launch_bounds__(256) void update1_kernel(
        const float* __restrict__ Wl, const float* __restrict__ wx, int dest) {
    int b = blockIdx.y;
    int i0 = blockIdx.x * 8;
    __shared__ __align__(16) float Ls[8 * 64];
    int tid = threadIdx.x;
    for (int t = tid; t < 512; t += 256)
        Ls[t] = g_L[((size_t)b * NN + i0) * 64 + t];
    __syncthreads();
    int h = tid & 63, iq = tid >> 6;
    float a0 = 0.f, a1 = 0.f;
#pragma unroll 8
    for (int hp = 0; hp < 64; hp++) {
        float wv = Wl[hp * 64 + h];
        a0 = fmaf(Ls[iq * 64 + hp],       wv, a0);
        a1 = fmaf(Ls[(iq + 4) * 64 + hp], wv, a1);
    }
    float wxh = wx[h];
    int i1 = i0 + iq, i2 = i0 + iq + 4;
    float v1 = fmaxf(a0 + g_xa[b * NN + i1] * wxh, 0.f);
    float v2 = fmaxf(a1 + g_xa[b * NN + i2] * wxh, 0.f);
    if (dest == 0) {
        g_U[((size_t)b * NN + i1) * 64 + h] = v1;
        g_U[((size_t)b * NN + i2) * 64 + h] = v2;
    } else {
        int off = (dest == 1) ? 0 : 64;
        g_UC[((size_t)b * NN + i1) * 128 + off + h] = v1;
        g_UC[((size_t)b * NN + i2) * 128 + off + h] = v2;
    }
}

// ---------------------------------------------------------------------------
// dense128: mode 0: g_X2 = g_UC @ W ; mode 1: g_G = relu(g_L @ W + g_X2)
// ---------------------------------------------------------------------------
__global__ __launch_bounds__(256) void dense128_kernel(
        const float* __restrict__ W, int mode) {
    int b = blockIdx.y;
    int i0 = blockIdx.x * 8;
    __shared__ __align__(16) float Ls[8 * 128];
    const float* In = (mode == 0) ? g_UC : g_L;
    int tid = threadIdx.x;
    for (int t = tid; t < 1024; t += 256)
        Ls[t] = In[((size_t)b * NN + i0) * 128 + t];
    __syncthreads();
    int h = tid & 127, iq = tid >> 7;
    float a[4] = {0.f, 0.f, 0.f, 0.f};
#pragma unroll 8
    for (int hp = 0; hp < 128; hp++) {
        float wv = W[hp * 128 + h];
#pragma unroll
        for (int u = 0; u < 4; u++)
            a[u] = fmaf(Ls[(iq + 2 * u) * 128 + hp], wv, a[u]);
    }
#pragma unroll
    for (int u = 0; u < 4; u++) {
        int i = i0 + iq + 2 * u;
        size_t o = ((size_t)b * NN + i) * 128 + h;
        if (mode == 1) g_G[o] = fmaxf(a[u] + g_X2[o], 0.f);
        else           g_X2[o] = a[u];
    }
}

// ---------------------------------------------------------------------------
// Q[b] = sum_{i,h} gamma[b,i,h] * WQ[h]
// ---------------------------------------------------------------------------
__global__ void qreduce_kernel(const float* __restrict__ WQ, float* __restrict__ out) {
    int b = blockIdx.x;
    int tid = threadIdx.x;
    const float* G = g_G + (size_t)b * NN * 128;
    float s = 0.f;
    for (int idx = tid; idx < NN * 128; idx += 256) {
        int h = idx & 127;
        s = fmaf(G[idx], WQ[h], s);
    }
    __shared__ float red[256];
    red[tid] = s; __syncthreads();
    for (int k = 128; k > 0; k >>= 1) {
        if (tid < k) red[tid] += red[tid + k];
        __syncthreads();
    }
    if (tid == 0) out[b] = red[0];
}

// ---------------------------------------------------------------------------
extern "C" void kernel_launch(void* const* d_in, const int* in_sizes, int n_in,
                              void* d_out, int out_size) {
    (void)in_sizes; (void)n_in; (void)out_size;
    const float* x_a_state = (const float*)d_in[0];
    const float* assign_pr = (const float*)d_in[1];
    const float* action    = (const float*)d_in[2];
    const float* edge      = (const float*)d_in[3];
    const float* avail     = (const float*)d_in[4];
    const float* u_a0      = (const float*)d_in[5];
    // d_in[6] = u_b0 : dead in reference
    const float* gamma0    = (const float*)d_in[7];
    const float* W1p       = (const float*)d_in[8];
    const float* W2p       = (const float*)d_in[9];
    const float* W_x_1a    = (const float*)d_in[10];
    const float* W_emb_1a  = (const float*)d_in[11];
    const float* W_l_1a    = (const float*)d_in[12];
    const float* W_x_1b    = (const float*)d_in[13];
    // d_in[14] = W_emb_1b : dead (l_a reuse bug kept)
    const float* W_l_1b    = (const float*)d_in[15];
    const float* W_x_2     = (const float*)d_in[16];
    const float* W_emb_2   = (const float*)d_in[17];
    const float* W_l_2     = (const float*)d_in[18];
    const float* W_Q       = (const float*)d_in[19];
    float* outp = (float*)d_out;

    xa_kernel<<<(NB * NN + 255) / 256, 256>>>(x_a_state, assign_pr, action);
    wpow_kernel<<<1, 128>>>(W_emb_1a, W_emb_2);
    presence_kernel<<<dim3(CC, NB), 256>>>(edge, avail, W1p, W2p);

    // ---- T1 ----
    for (int t = 0; t < 5; t++) {
        buildB_kernel<<<dim3(16, NB), 256>>>(t == 0 ? 0 : 1, u_a0, 64, 0);
        gemm_kernel<64><<<dim3(16, NB), 256>>>();
        if (t < 4) {
            update1_kernel<<<dim3(128, NB), 256>>>(W_l_1a, W_x_1a, 0);
        } else {
            update1_kernel<<<dim3(128, NB), 256>>>(W_l_1a, W_x_1a, 1);
            update1_kernel<<<dim3(128, NB), 256>>>(W_l_1b, W_x_1b, 2);
        }
    }
    dense128_kernel<<<dim3(128, NB), 256>>>(W_x_2, 0);

    // ---- T2 ----
    for (int t = 0; t < 5; t++) {
        buildB_kernel<<<dim3(16, NB), 256>>>(t == 0 ? 0 : 2, gamma0, 128, 1);
        gemm_kernel<128><<<dim3(16, NB), 256>>>();
        dense128_kernel<<<dim3(128, NB), 256>>>(W_l_2, 1);
    }

    qreduce_kernel<<<NB, 256>>>(W_Q, outp);
}

// round 12
// speedup vs baseline: 4.7682x; 1.0417x over previous
#include <cuda_runtime.h>
#include <cuda_fp16.h>
#include <math.h>
#include <stdint.h>

// ============================================================================
// Model_90168543412725 — graph attention Q network
// B=16, C=1023 cities, N=1024 nodes, H=64, T1=T2=5
//
// sigmoid(d*w), |d*w|<=1 -> deg-7 odd Taylor -> per-iteration GEMM,
// kappa = k*1024 + c (c=1023 rows of Pk stay zero => Bt garbage there is
// annihilated; 1024-alignment gives coalesced buildB stores).
//   l[b,i,h] = sum_{k,c} (P[b,i,c] d^k) * (a_k w_h^k u[b,c,h])
// Engine: mma.sync.m16n8k16 fp16, fp32 accum, 4-stage cp.async pipeline.
// ============================================================================

#define NB 16
#define CC 1023
#define NN 1024
#define KPAD 5120
#define KCH 64
#define NCHUNK (KPAD / KCH)            // 80
#define PSE ((size_t)NN * NN)          // Pk plane stride (k -> k+1), elements

// ---- scratch (device globals; .bss zero-init — pad rows stay zero) ----
__device__ __align__(16) __half g_Pk [(size_t)NB * KPAD * NN];   // [b][kappa][i]
__device__ __align__(16) __half g_Bt1[(size_t)NB * 128 * KPAD];  // [b][h][kappa]
__device__ __align__(16) __half g_Bt2[(size_t)NB * 128 * KPAD];
__device__ __align__(16) float g_L [NB * NN * 128];
__device__ __align__(16) float g_U [NB * NN * 64];
__device__ __align__(16) float g_UC[NB * NN * 128];
__device__ __align__(16) float g_X2[NB * NN * 128];
__device__ __align__(16) float g_G [NB * NN * 128];
__device__ float g_xa[NB * NN];
__device__ float g_wp1[5 * 64];
__device__ float g_wp2[5 * 128];

// ---------------------------------------------------------------------------
__device__ __forceinline__ uint32_t s2u(const void* p) {
    uint32_t a;
    asm("{ .reg .u64 t; cvta.to.shared.u64 t, %1; cvt.u32.u64 %0, t; }"
        : "=r"(a) : "l"(p));
    return a;
}
#define SWZ(x) ((x) ^ (((x) >> 3) & 0x70))

#define LDSM_X4(r, addr)                                                      \
    asm volatile("ldmatrix.sync.aligned.m8n8.x4.shared.b16 {%0,%1,%2,%3}, [%4];" \
        : "=r"((r)[0]), "=r"((r)[1]), "=r"((r)[2]), "=r"((r)[3]) : "r"(addr))
#define LDSM_X2T(r, addr)                                                     \
    asm volatile("ldmatrix.sync.aligned.m8n8.x2.trans.shared.b16 {%0,%1}, [%2];" \
        : "=r"((r)[0]), "=r"((r)[1]) : "r"(addr))
#define MMA16816(d, a, bb)                                                    \
    asm volatile(                                                             \
        "mma.sync.aligned.m16n8k16.row.col.f32.f16.f16.f32 "                  \
        "{%0,%1,%2,%3}, {%4,%5,%6,%7}, {%8,%9}, {%0,%1,%2,%3};"               \
        : "+f"((d)[0]), "+f"((d)[1]), "+f"((d)[2]), "+f"((d)[3])              \
        : "r"((a)[0]), "r"((a)[1]), "r"((a)[2]), "r"((a)[3]),                 \
          "r"((bb)[0]), "r"((bb)[1]))
#define CP_ASYNC16(s, g)                                                      \
    asm volatile("cp.async.cg.shared.global [%0], [%1], 16;"                  \
        :: "r"(s), "l"(g) : "memory")
#define CP_COMMIT() asm volatile("cp.async.commit_group;" ::: "memory")
#define CP_WAIT(n)  asm volatile("cp.async.wait_group %0;" :: "n"(n) : "memory")

// ---------------------------------------------------------------------------
// x_a[b,n] = max_r x_a_state[b,r,n] * (assignment_prev + action)[b,r,n]
// ---------------------------------------------------------------------------
__global__ void xa_kernel(const float* __restrict__ xs,
                          const float* __restrict__ ap,
                          const float* __restrict__ act) {
    int idx = blockIdx.x * 256 + threadIdx.x;
    if (idx >= NB * NN) return;
    int b = idx >> 10, n = idx & 1023;
    float mx = -3.4e38f;
#pragma unroll
    for (int r = 0; r < 8; r++) {
        int o = (b * 8 + r) * NN + n;
        mx = fmaxf(mx, xs[o] * (ap[o] + act[o]));
    }
    g_xa[idx] = mx;
}

// ---------------------------------------------------------------------------
// wp[k][h] = a_k * w_h^pow(k),  pow = {0,1,3,5,7}
// ---------------------------------------------------------------------------
__global__ void wpow_kernel(const float* __restrict__ w1a,
                            const float* __restrict__ w2) {
    const float a0 = 0.5f, a1 = 0.25f, a3 = -1.f/48.f,
                a5 = 1.f/480.f, a7 = -17.f/80640.f;
    int h = threadIdx.x;
    if (h < 64) {
        float w = w1a[h]; float ww = w * w;
        float w3 = w * ww, w5 = w3 * ww, w7 = w5 * ww;
        g_wp1[0*64+h] = a0;     g_wp1[1*64+h] = a1*w;
        g_wp1[2*64+h] = a3*w3;  g_wp1[3*64+h] = a5*w5;
        g_wp1[4*64+h] = a7*w7;
    }
    if (h < 128) {
        float w = w2[h]; float ww = w * w;
        float w3 = w * ww, w5 = w3 * ww, w7 = w5 * ww;
        g_wp2[0*128+h] = a0;    g_wp2[1*128+h] = a1*w;
        g_wp2[2*128+h] = a3*w3; g_wp2[3*128+h] = a5*w5;
        g_wp2[4*128+h] = a7*w7;
    }
}

// ---------------------------------------------------------------------------
// Presence attention + Pk build (fp16). One block per (b,c).
// Pk[b][k*1024+c][n] = softmax_n(logit)[n] * d(n)^pow(k)
// ---------------------------------------------------------------------------
__global__ __launch_bounds__(256) void presence_kernel(
        const float* __restrict__ edge, const float* __restrict__ avail,
        const float* __restrict__ W1, const float* __restrict__ W2) {
    const int c = blockIdx.x;
    const int b = blockIdx.y;
    __shared__ __align__(16) float4 w4[64];
    __shared__ float lbuf[1024];
    __shared__ float dbuf[1024];
    __shared__ float red[256];
    int tid = threadIdx.x;
    if (tid < 64) w4[tid] = make_float4(W1[tid], W1[64+tid], W1[128+tid], W2[tid]);
    __syncthreads();

    for (int n = tid; n < NN; n += 256) {
        size_t base = ((size_t)(b * CC + c) * NN + n) * 3;
        float e0 = edge[base], e1 = edge[base+1], e2 = edge[base+2];
        float s = 0.f;
#pragma unroll 16
        for (int j = 0; j < 64; j++) {
            float4 w = w4[j];
            float h = fmaf(e0, w.x, fmaf(e1, w.y, e2 * w.z));
            h = fmaxf(h, 0.f);
            s = fmaf(h, w.w, s);
        }
        float h2 = fmaxf(s, 0.f);
        float m = (n == c ? 0.f : 1.f) * avail[b * NN + n];
        lbuf[n] = h2 * m - (1.f - m) * 1e10f;
        dbuf[n] = e0;
    }
    __syncthreads();

    float mx = -3.4e38f;
    for (int n = tid; n < NN; n += 256) mx = fmaxf(mx, lbuf[n]);
    red[tid] = mx; __syncthreads();
    for (int k = 128; k > 0; k >>= 1) {
        if (tid < k) red[tid] = fmaxf(red[tid], red[tid + k]);
        __syncthreads();
    }
    mx = red[0];

    float sm = 0.f;
    for (int n = tid; n < NN; n += 256) {
        float e = __expf(lbuf[n] - mx);
        lbuf[n] = e; sm += e;
    }
    __syncthreads();
    red[tid] = sm; __syncthreads();
    for (int k = 128; k > 0; k >>= 1) {
        if (tid < k) red[tid] += red[tid + k];
        __syncthreads();
    }
    float inv = 1.f / red[0];

    for (int n = tid; n < NN; n += 256) {
        float p = lbuf[n] * inv;
        float d = dbuf[n];
        float d2 = d * d;
        size_t i0 = ((size_t)b * KPAD + c) * NN + n;   // kappa = k*1024 + c
        g_Pk[i0]           = __float2half(p);
        float q = p * d;  g_Pk[i0 + PSE]     = __float2half(q);
        q *= d2;          g_Pk[i0 + 2 * PSE] = __float2half(q);
        q *= d2;          g_Pk[i0 + 3 * PSE] = __float2half(q);
        q *= d2;          g_Pk[i0 + 4 * PSE] = __float2half(q);
    }
}

// ---------------------------------------------------------------------------
// buildB (transpose): Bt[b][h][k*1024+c] = wp[k][h] * U[b][c][h]  (fp16)
// Coalesced half2 stores (c0 64-aligned, plane base 1024-aligned).
// c=1023 entries are garbage — multiplied by Pk's zero pad rows in the GEMM.
// sel: 0 -> ext, 1 -> g_U, 2 -> g_G.  phase: 0 -> Bt1, 1 -> Bt2.
// ---------------------------------------------------------------------------
__global__ __launch_bounds__(256) void buildB_kernel(int sel, const float* __restrict__ ext,
                                                     int NH, int phase) {
    int b = blockIdx.y, c0 = blockIdx.x * 64;
    __shared__ float Us[64 * 129];
    const int stride = NH + 1;
    const float* U = (sel == 0) ? ext : (sel == 1 ? g_U : g_G);
    const float* wp = (NH == 64) ? g_wp1 : g_wp2;
    __half* Bt = phase ? g_Bt2 : g_Bt1;
    int tid = threadIdx.x;
    for (int idx = tid; idx < 64 * NH; idx += 256) {
        int cl = idx / NH, h = idx - cl * NH;
        Us[cl * stride + h] = U[((size_t)b * NN + c0 + cl) * NH + h];
    }
    __syncthreads();
    int w = tid >> 5, l = tid & 31;
    for (int r = w; r < NH * 5; r += 8) {
        int k = r / NH;
        int h = r - k * NH;
        float s = wp[k * NH + h];
        __half2 v = __floats2half2_rn(s * Us[(2 * l) * stride + h],
                                      s * Us[(2 * l + 1) * stride + h]);
        *(__half2*)(Bt + ((size_t)b * 128 + h) * KPAD + k * 1024 + c0 + 2 * l) = v;
    }
}

// ---------------------------------------------------------------------------
// fp16 GEMM via mma.sync m16n8k16:
//   L[b][i][h] = sum_kappa Bt[b][h][kappa] * Pk[b][kappa][i]
// D[m=h(NH)][n=i(64)]. A (Bt) row-major over kappa -> ldmatrix.x4.
// B (Pk) [kappa][i] -> ldmatrix.x2.trans -> col-major B fragment.
// SW128 XOR swizzle; 4-stage cp.async pipeline (1 sync/chunk);
// smem-staged coalesced epilogue. grid (16 i-tiles, NB), 256 thr / 8 warps.
// ---------------------------------------------------------------------------
template<int NH>
__global__ void __launch_bounds__(256) gemm_kernel() {
    constexpr int ASZ = NH * 128;          // bytes per A stage
    constexpr int BSZ = 64 * 128;          // 8 KB per B stage
    constexpr int STG = ASZ + BSZ;
    constexpr int WN  = (NH == 128) ? 2 : 4;
    constexpr int NTI = (NH == 128) ? 4 : 2;
    extern __shared__ __align__(128) char smem[];

    const int b = blockIdx.y;
    const int i0 = blockIdx.x * 64;
    const __half* Ag = (NH == 64 ? g_Bt1 : g_Bt2) + (size_t)b * 128 * KPAD;
    const __half* Bg = g_Pk + (size_t)b * KPAD * NN + i0;

    const int tid = threadIdx.x, lane = tid & 31, wid = tid >> 5;
    const int wm = wid / WN, wn = wid % WN;
    const uint32_t sb = s2u(smem);

    float acc[2][NTI][4];
#pragma unroll
    for (int mi = 0; mi < 2; mi++)
#pragma unroll
        for (int ni = 0; ni < NTI; ni++)
#pragma unroll
            for (int q = 0; q < 4; q++) acc[mi][ni][q] = 0.f;

    const int gr = tid >> 3;           // 0..31
    const int gc = (tid & 7) * 16;     // byte col

    auto load_stage = [&](int ch) {
        uint32_t Ss = sb + (ch & 3) * STG;
        size_t k0 = (size_t)ch * KCH;
#pragma unroll
        for (int p = 0; p < ASZ / 4096; p++) {
            int r = p * 32 + gr;
            CP_ASYNC16(Ss + SWZ(r * 128 + gc),
                       (const char*)(Ag + (size_t)r * KPAD + k0) + gc);
        }
#pragma unroll
        for (int p = 0; p < 2; p++) {
            int r = p * 32 + gr;
            CP_ASYNC16(Ss + ASZ + SWZ(r * 128 + gc),
                       (const char*)(Bg + (k0 + r) * NN) + gc);
        }
    };

    load_stage(0); CP_COMMIT();
    load_stage(1); CP_COMMIT();
    load_stage(2); CP_COMMIT();

    for (int ch = 0; ch < NCHUNK; ch++) {
        CP_WAIT(2);
        __syncthreads();
        if (ch + 3 < NCHUNK) load_stage(ch + 3);
        CP_COMMIT();

        const uint32_t Ab = sb + (ch & 3) * STG;
        const uint32_t Bb = Ab + ASZ;
#pragma unroll
        for (int kk = 0; kk < 4; kk++) {
            uint32_t af[2][4];
#pragma unroll
            for (int mi = 0; mi < 2; mi++) {
                int r = wm * 32 + mi * 16 + (lane & 15);
                int c = kk * 16 + ((lane >> 4) << 3);
                LDSM_X4(af[mi], Ab + SWZ(r * 128 + c * 2));
            }
            uint32_t bf[NTI][2];
#pragma unroll
            for (int ni = 0; ni < NTI; ni++) {
                int r = kk * 16 + (lane & 15);
                int c = wn * (NTI * 8) + ni * 8;
                LDSM_X2T(bf[ni], Bb + SWZ(r * 128 + c * 2));
            }
#pragma unroll
            for (int mi = 0; mi < 2; mi++)
#pragma unroll
                for (int ni = 0; ni < NTI; ni++)
                    MMA16816(acc[mi][ni], af[mi], bf[ni]);
        }
    }

    // ---- epilogue: stage through smem, then coalesced store to L[b][i][h] ----
    __syncthreads();
    float* Cs = (float*)smem;              // [64][NH+1]
    const int g = lane >> 2, tg = lane & 3;
#pragma unroll
    for (int mi = 0; mi < 2; mi++) {
        int h0 = wm * 32 + mi * 16 + g;
#pragma unroll
        for (int ni = 0; ni < NTI; ni++) {
            int ic = wn * (NTI * 8) + ni * 8 + tg * 2;
            Cs[ic * (NH + 1) + h0]           = acc[mi][ni][0];
            Cs[(ic + 1) * (NH + 1) + h0]     = acc[mi][ni][1];
            Cs[ic * (NH + 1) + h0 + 8]       = acc[mi][ni][2];
            Cs[(ic + 1) * (NH + 1) + h0 + 8] = acc[mi][ni][3];
        }
    }
    __syncthreads();
    float* Lp = g_L + ((size_t)b * NN + i0) * NH;
    for (int t = tid; t < 64 * NH; t += 256) {
        int ic = t / NH, h = t - ic * NH;
        Lp[t] = Cs[ic * (NH + 1) + h];
    }
}

// ---------------------------------------------------------------------------
// T1 update: out = relu(L @ Wl + xa * wx);  dest 0 -> g_U, 1/2 -> g_UC halves
// ---------------------------------------------------------------------------
__global__ __launch_bounds__(256) void update1_kernel(
        const float* __restrict__ Wl, const float* __restrict__ wx, int dest) {
    int b = blockIdx.y;
    int i0 = blockIdx.x * 8;
    __shared__ __align__(16) float Ls[8 * 64];
    int tid = threadIdx.x;
    for (int t = tid; t < 512; t += 256)
        Ls[t] = g_L[((size_t)b * NN + i0) * 64 + t];
    __syncthreads();
    int h = tid & 63, iq = tid >> 6;
    float a0 = 0.f, a1 = 0.f;
#pragma unroll 8
    for (int hp = 0; hp < 64; hp++) {
        float wv = Wl[hp * 64 + h];
        a0 = fmaf(Ls[iq * 64 + hp],       wv, a0);
        a1 = fmaf(Ls[(iq + 4) * 64 + hp], wv, a1);
    }
    float wxh = wx[h];
    int i1 = i0 + iq, i2 = i0 + iq + 4;
    float v1 = fmaxf(a0 + g_xa[b * NN + i1] * wxh, 0.f);
    float v2 = fmaxf(a1 + g_xa[b * NN + i2] * wxh, 0.f);
    if (dest == 0) {
        g_U[((size_t)b * NN + i1) * 64 + h] = v1;
        g_U[((size_t)b * NN + i2) * 64 + h] = v2;
    } else {
        int off = (dest == 1) ? 0 : 64;
        g_UC[((size_t)b * NN + i1) * 128 + off + h] = v1;
        g_UC[((size_t)b * NN + i2) * 128 + off + h] = v2;
    }
}

// ---------------------------------------------------------------------------
// dense128: mode 0: g_X2 = g_UC @ W ; mode 1: g_G = relu(g_L @ W + g_X2)
// ---------------------------------------------------------------------------
__global__ __launch_bounds__(256) void dense128_kernel(
        const float* __restrict__ W, int mode) {
    int b = blockIdx.y;
    int i0 = blockIdx.x * 8;
    __shared__ __align__(16) float Ls[8 * 128];
    const float* In = (mode == 0) ? g_UC : g_L;
    int tid = threadIdx.x;
    for (int t = tid; t < 1024; t += 256)
        Ls[t] = In[((size_t)b * NN + i0) * 128 + t];
    __syncthreads();
    int h = tid & 127, iq = tid >> 7;
    float a[4] = {0.f, 0.f, 0.f, 0.f};
#pragma unroll 8
    for (int hp = 0; hp < 128; hp++) {
        float wv = W[hp * 128 + h];
#pragma unroll
        for (int u = 0; u < 4; u++)
            a[u] = fmaf(Ls[(iq + 2 * u) * 128 + hp], wv, a[u]);
    }
#pragma unroll
    for (int u = 0; u < 4; u++) {
        int i = i0 + iq + 2 * u;
        size_t o = ((size_t)b * NN + i) * 128 + h;
        if (mode == 1) g_G[o] = fmaxf(a[u] + g_X2[o], 0.f);
        else           g_X2[o] = a[u];
    }
}

// ---------------------------------------------------------------------------
// Q[b] = sum_{i,h} gamma[b,i,h] * WQ[h]
// ---------------------------------------------------------------------------
__global__ void qreduce_kernel(const float* __restrict__ WQ, float* __restrict__ out) {
    int b = blockIdx.x;
    int tid = threadIdx.x;
    const float* G = g_G + (size_t)b * NN * 128;
    float s = 0.f;
    for (int idx = tid; idx < NN * 128; idx += 256) {
        int h = idx & 127;
        s = fmaf(G[idx], WQ[h], s);
    }
    __shared__ float red[256];
    red[tid] = s; __syncthreads();
    for (int k = 128; k > 0; k >>= 1) {
        if (tid < k) red[tid] += red[tid + k];
        __syncthreads();
    }
    if (tid == 0) out[b] = red[0];
}

// ---------------------------------------------------------------------------
extern "C" void kernel_launch(void* const* d_in, const int* in_sizes, int n_in,
                              void* d_out, int out_size) {
    (void)in_sizes; (void)n_in; (void)out_size;
    const float* x_a_state = (const float*)d_in[0];
    const float* assign_pr = (const float*)d_in[1];
    const float* action    = (const float*)d_in[2];
    const float* edge      = (const float*)d_in[3];
    const float* avail     = (const float*)d_in[4];
    const float* u_a0      = (const float*)d_in[5];
    // d_in[6] = u_b0 : dead in reference
    const float* gamma0    = (const float*)d_in[7];
    const float* W1p       = (const float*)d_in[8];
    const float* W2p       = (const float*)d_in[9];
    const float* W_x_1a    = (const float*)d_in[10];
    const float* W_emb_1a  = (const float*)d_in[11];
    const float* W_l_1a    = (const float*)d_in[12];
    const float* W_x_1b    = (const float*)d_in[13];
    // d_in[14] = W_emb_1b : dead (l_a reuse bug kept)
    const float* W_l_1b    = (const float*)d_in[15];
    const float* W_x_2     = (const float*)d_in[16];
    const float* W_emb_2   = (const float*)d_in[17];
    const float* W_l_2     = (const float*)d_in[18];
    const float* W_Q       = (const float*)d_in[19];
    float* outp = (float*)d_out;

    const int SM64  = 4 * (64 * 128 + 8192);    // 64 KB
    const int SM128 = 4 * (128 * 128 + 8192);   // 96 KB
    cudaFuncSetAttribute(gemm_kernel<64>,
                         cudaFuncAttributeMaxDynamicSharedMemorySize, SM64);
    cudaFuncSetAttribute(gemm_kernel<128>,
                         cudaFuncAttributeMaxDynamicSharedMemorySize, SM128);

    xa_kernel<<<(NB * NN + 255) / 256, 256>>>(x_a_state, assign_pr, action);
    wpow_kernel<<<1, 128>>>(W_emb_1a, W_emb_2);
    presence_kernel<<<dim3(CC, NB), 256>>>(edge, avail, W1p, W2p);

    // ---- T1 ----
    for (int t = 0; t < 5; t++) {
        buildB_kernel<<<dim3(16, NB), 256>>>(t == 0 ? 0 : 1, u_a0, 64, 0);
        gemm_kernel<64><<<dim3(16, NB), 256, SM64>>>();
        if (t < 4) {
            update1_kernel<<<dim3(128, NB), 256>>>(W_l_1a, W_x_1a, 0);
        } else {
            update1_kernel<<<dim3(128, NB), 256>>>(W_l_1a, W_x_1a, 1);
            update1_kernel<<<dim3(128, NB), 256>>>(W_l_1b, W_x_1b, 2);
        }
    }
    dense128_kernel<<<dim3(128, NB), 256>>>(W_x_2, 0);

    // ---- T2 ----
    for (int t = 0; t < 5; t++) {
        buildB_kernel<<<dim3(16, NB), 256>>>(t == 0 ? 0 : 2, gamma0, 128, 1);
        gemm_kernel<128><<<dim3(16, NB), 256, SM128>>>();
        dense128_kernel<<<dim3(128, NB), 256>>>(W_l_2, 1);
    }

    qreduce_kernel<<<NB, 256>>>(W_Q, outp);
}

// round 13
// speedup vs baseline: 5.3396x; 1.1198x over previous
#include <cuda_runtime.h>
#include <cuda_fp16.h>
#include <math.h>
#include <stdint.h>

// ============================================================================
// Model_90168543412725 — graph attention Q network
// B=16, C=1023 cities, N=1024 nodes, H=64, T1=T2=5
//
// sigmoid(d*w), |d*w|<=1 -> deg-7 odd Taylor -> per-iteration GEMM,
// kappa = k*1024 + c (c=1023 rows of Pk stay zero => Bt garbage there is
// annihilated; 1024-alignment gives coalesced buildB stores).
//   l[b,i,h] = sum_{k,c} (P[b,i,c] d^k) * (a_k w_h^k u[b,c,h])
// Engine: mma.sync.m16n8k16 fp16, fp32 accum, 4-stage cp.async pipeline.
// Presence MLP in packed half2 (errors independent per (c,n) -> wash out).
// ============================================================================

#define NB 16
#define CC 1023
#define NN 1024
#define KPAD 5120
#define KCH 64
#define NCHUNK (KPAD / KCH)            // 80
#define PSE ((size_t)NN * NN)          // Pk plane stride (k -> k+1), elements

// ---- scratch (device globals; .bss zero-init — pad rows stay zero) ----
__device__ __align__(16) __half g_Pk [(size_t)NB * KPAD * NN];   // [b][kappa][i]
__device__ __align__(16) __half g_Bt1[(size_t)NB * 128 * KPAD];  // [b][h][kappa]
__device__ __align__(16) __half g_Bt2[(size_t)NB * 128 * KPAD];
__device__ __align__(16) float g_L [NB * NN * 128];
__device__ __align__(16) float g_U [NB * NN * 64];
__device__ __align__(16) float g_UC[NB * NN * 128];
__device__ __align__(16) float g_X2[NB * NN * 128];
__device__ __align__(16) float g_G [NB * NN * 128];
__device__ float g_xa[NB * NN];
__device__ float g_wp1[5 * 64];
__device__ float g_wp2[5 * 128];

// ---------------------------------------------------------------------------
__device__ __forceinline__ uint32_t s2u(const void* p) {
    uint32_t a;
    asm("{ .reg .u64 t; cvta.to.shared.u64 t, %1; cvt.u32.u64 %0, t; }"
        : "=r"(a) : "l"(p));
    return a;
}
#define SWZ(x) ((x) ^ (((x) >> 3) & 0x70))

#define LDSM_X4(r, addr)                                                      \
    asm volatile("ldmatrix.sync.aligned.m8n8.x4.shared.b16 {%0,%1,%2,%3}, [%4];" \
        : "=r"((r)[0]), "=r"((r)[1]), "=r"((r)[2]), "=r"((r)[3]) : "r"(addr))
#define LDSM_X2T(r, addr)                                                     \
    asm volatile("ldmatrix.sync.aligned.m8n8.x2.trans.shared.b16 {%0,%1}, [%2];" \
        : "=r"((r)[0]), "=r"((r)[1]) : "r"(addr))
#define MMA16816(d, a, bb)                                                    \
    asm volatile(                                                             \
        "mma.sync.aligned.m16n8k16.row.col.f32.f16.f16.f32 "                  \
        "{%0,%1,%2,%3}, {%4,%5,%6,%7}, {%8,%9}, {%0,%1,%2,%3};"               \
        : "+f"((d)[0]), "+f"((d)[1]), "+f"((d)[2]), "+f"((d)[3])              \
        : "r"((a)[0]), "r"((a)[1]), "r"((a)[2]), "r"((a)[3]),                 \
          "r"((bb)[0]), "r"((bb)[1]))
#define CP_ASYNC16(s, g)                                                      \
    asm volatile("cp.async.cg.shared.global [%0], [%1], 16;"                  \
        :: "r"(s), "l"(g) : "memory")
#define CP_COMMIT() asm volatile("cp.async.commit_group;" ::: "memory")
#define CP_WAIT(n)  asm volatile("cp.async.wait_group %0;" :: "n"(n) : "memory")

// ---------------------------------------------------------------------------
// x_a[b,n] = max_r x_a_state[b,r,n] * (assignment_prev + action)[b,r,n]
// ---------------------------------------------------------------------------
__global__ void xa_kernel(const float* __restrict__ xs,
                          const float* __restrict__ ap,
                          const float* __restrict__ act) {
    int idx = blockIdx.x * 256 + threadIdx.x;
    if (idx >= NB * NN) return;
    int b = idx >> 10, n = idx & 1023;
    float mx = -3.4e38f;
#pragma unroll
    for (int r = 0; r < 8; r++) {
        int o = (b * 8 + r) * NN + n;
        mx = fmaxf(mx, xs[o] * (ap[o] + act[o]));
    }
    g_xa[idx] = mx;
}

// ---------------------------------------------------------------------------
// wp[k][h] = a_k * w_h^pow(k),  pow = {0,1,3,5,7}
// ---------------------------------------------------------------------------
__global__ void wpow_kernel(const float* __restrict__ w1a,
                            const float* __restrict__ w2) {
    const float a0 = 0.5f, a1 = 0.25f, a3 = -1.f/48.f,
                a5 = 1.f/480.f, a7 = -17.f/80640.f;
    int h = threadIdx.x;
    if (h < 64) {
        float w = w1a[h]; float ww = w * w;
        float w3 = w * ww, w5 = w3 * ww, w7 = w5 * ww;
        g_wp1[0*64+h] = a0;     g_wp1[1*64+h] = a1*w;
        g_wp1[2*64+h] = a3*w3;  g_wp1[3*64+h] = a5*w5;
        g_wp1[4*64+h] = a7*w7;
    }
    if (h < 128) {
        float w = w2[h]; float ww = w * w;
        float w3 = w * ww, w5 = w3 * ww, w7 = w5 * ww;
        g_wp2[0*128+h] = a0;    g_wp2[1*128+h] = a1*w;
        g_wp2[2*128+h] = a3*w3; g_wp2[3*128+h] = a5*w5;
        g_wp2[4*128+h] = a7*w7;
    }
}

// ---------------------------------------------------------------------------
// Presence attention + Pk build. One block per (b,c).
// MLP h1/h2 in packed half2 (HFMA2), softmax + Pk in fp32/fp16.
// Pk[b][k*1024+c][n] = softmax_n(logit)[n] * d(n)^pow(k)
// ---------------------------------------------------------------------------
__global__ __launch_bounds__(256) void presence_kernel(
        const float* __restrict__ edge, const float* __restrict__ avail,
        const float* __restrict__ W1, const float* __restrict__ W2) {
    const int c = blockIdx.x;
    const int b = blockIdx.y;
    __shared__ __align__(16) uint4 wpk[32];   // [j] = {wx2, wy2, wz2, w22}
    __shared__ float lbuf[1024];
    __shared__ float dbuf[1024];
    __shared__ float red[256];
    int tid = threadIdx.x;
    if (tid < 32) {
        int j = tid;
        __half2 wx = __floats2half2_rn(W1[2*j],       W1[2*j + 1]);
        __half2 wy = __floats2half2_rn(W1[64 + 2*j],  W1[64 + 2*j + 1]);
        __half2 wz = __floats2half2_rn(W1[128 + 2*j], W1[128 + 2*j + 1]);
        __half2 w2 = __floats2half2_rn(W2[2*j],       W2[2*j + 1]);
        uint4 v;
        v.x = *(uint32_t*)&wx; v.y = *(uint32_t*)&wy;
        v.z = *(uint32_t*)&wz; v.w = *(uint32_t*)&w2;
        wpk[j] = v;
    }
    __syncthreads();

    float e0s[4];
    __half2 E0[4], E1[4], E2[4], S[4];
    const __half2 zero2 = __float2half2_rn(0.f);
#pragma unroll
    for (int q = 0; q < 4; q++) {
        int n = tid + q * 256;
        size_t base = ((size_t)(b * CC + c) * NN + n) * 3;
        float e0 = edge[base], e1 = edge[base + 1], e2 = edge[base + 2];
        e0s[q] = e0;
        E0[q] = __float2half2_rn(e0);
        E1[q] = __float2half2_rn(e1);
        E2[q] = __float2half2_rn(e2);
        S[q] = zero2;
    }
#pragma unroll 8
    for (int j = 0; j < 32; j++) {
        uint4 v = wpk[j];
        __half2 wx = *(__half2*)&v.x, wy = *(__half2*)&v.y;
        __half2 wz = *(__half2*)&v.z, w2 = *(__half2*)&v.w;
#pragma unroll
        for (int q = 0; q < 4; q++) {
            __half2 t = __hfma2(E0[q], wx, __hfma2(E1[q], wy, __hmul2(E2[q], wz)));
            t = __hmax2(t, zero2);
            S[q] = __hfma2(t, w2, S[q]);
        }
    }
#pragma unroll
    for (int q = 0; q < 4; q++) {
        int n = tid + q * 256;
        float h2 = fmaxf(__low2float(S[q]) + __high2float(S[q]), 0.f);
        float m = (n == c ? 0.f : 1.f) * avail[b * NN + n];
        lbuf[n] = h2 * m - (1.f - m) * 1e10f;
        dbuf[n] = e0s[q];
    }
    __syncthreads();

    float mx = -3.4e38f;
    for (int n = tid; n < NN; n += 256) mx = fmaxf(mx, lbuf[n]);
    red[tid] = mx; __syncthreads();
    for (int k = 128; k > 0; k >>= 1) {
        if (tid < k) red[tid] = fmaxf(red[tid], red[tid + k]);
        __syncthreads();
    }
    mx = red[0];

    float sm = 0.f;
    for (int n = tid; n < NN; n += 256) {
        float e = __expf(lbuf[n] - mx);
        lbuf[n] = e; sm += e;
    }
    __syncthreads();
    red[tid] = sm; __syncthreads();
    for (int k = 128; k > 0; k >>= 1) {
        if (tid < k) red[tid] += red[tid + k];
        __syncthreads();
    }
    float inv = 1.f / red[0];

    for (int n = tid; n < NN; n += 256) {
        float p = lbuf[n] * inv;
        float d = dbuf[n];
        float d2 = d * d;
        size_t i0 = ((size_t)b * KPAD + c) * NN + n;   // kappa = k*1024 + c
        g_Pk[i0]           = __float2half(p);
        float q = p * d;  g_Pk[i0 + PSE]     = __float2half(q);
        q *= d2;          g_Pk[i0 + 2 * PSE] = __float2half(q);
        q *= d2;          g_Pk[i0 + 3 * PSE] = __float2half(q);
        q *= d2;          g_Pk[i0 + 4 * PSE] = __float2half(q);
    }
}

// ---------------------------------------------------------------------------
// buildB (transpose): Bt[b][h][k*1024+c] = wp[k][h] * U[b][c][h]  (fp16)
// grid (16 c-tiles, NB, 5 k) — k-split for 5x grid parallelism.
// Coalesced half2 stores. c=1023 entries are garbage — annihilated by Pk's
// zero pad rows. sel: 0 -> ext, 1 -> g_U, 2 -> g_G. phase: 0 -> Bt1, 1 -> Bt2.
// ---------------------------------------------------------------------------
__global__ __launch_bounds__(256) void buildB_kernel(int sel, const float* __restrict__ ext,
                                                     int NH, int phase) {
    int b = blockIdx.y, c0 = blockIdx.x * 64, k = blockIdx.z;
    __shared__ float Us[64 * 129];
    const int stride = NH + 1;
    const float* U = (sel == 0) ? ext : (sel == 1 ? g_U : g_G);
    const float* wp = (NH == 64) ? g_wp1 : g_wp2;
    __half* Bt = phase ? g_Bt2 : g_Bt1;
    int tid = threadIdx.x;
    for (int idx = tid; idx < 64 * NH; idx += 256) {
        int cl = idx / NH, h = idx - cl * NH;
        Us[cl * stride + h] = U[((size_t)b * NN + c0 + cl) * NH + h];
    }
    __syncthreads();
    int w = tid >> 5, l = tid & 31;
    for (int h = w; h < NH; h += 8) {
        float s = wp[k * NH + h];
        __half2 v = __floats2half2_rn(s * Us[(2 * l) * stride + h],
                                      s * Us[(2 * l + 1) * stride + h]);
        *(__half2*)(Bt + ((size_t)b * 128 + h) * KPAD + k * 1024 + c0 + 2 * l) = v;
    }
}

// ---------------------------------------------------------------------------
// fp16 GEMM via mma.sync m16n8k16:
//   L[b][i][h] = sum_kappa Bt[b][h][kappa] * Pk[b][kappa][i]
// D[m=h(NH)][n=i(64)]. A (Bt) row-major over kappa -> ldmatrix.x4.
// B (Pk) [kappa][i] -> ldmatrix.x2.trans -> col-major B fragment.
// SW128 XOR swizzle; 4-stage cp.async pipeline (1 sync/chunk);
// smem-staged coalesced epilogue. grid (16 i-tiles, NB), 256 thr / 8 warps.
// ---------------------------------------------------------------------------
template<int NH>
__global__ void __launch_bounds__(256) gemm_kernel() {
    constexpr int ASZ = NH * 128;          // bytes per A stage
    constexpr int BSZ = 64 * 128;          // 8 KB per B stage
    constexpr int STG = ASZ + BSZ;
    constexpr int WN  = (NH == 128) ? 2 : 4;
    constexpr int NTI = (NH == 128) ? 4 : 2;
    extern __shared__ __align__(128) char smem[];

    const int b = blockIdx.y;
    const int i0 = blockIdx.x * 64;
    const __half* Ag = (NH == 64 ? g_Bt1 : g_Bt2) + (size_t)b * 128 * KPAD;
    const __half* Bg = g_Pk + (size_t)b * KPAD * NN + i0;

    const int tid = threadIdx.x, lane = tid & 31, wid = tid >> 5;
    const int wm = wid / WN, wn = wid % WN;
    const uint32_t sb = s2u(smem);

    float acc[2][NTI][4];
#pragma unroll
    for (int mi = 0; mi < 2; mi++)
#pragma unroll
        for (int ni = 0; ni < NTI; ni++)
#pragma unroll
            for (int q = 0; q < 4; q++) acc[mi][ni][q] = 0.f;

    const int gr = tid >> 3;           // 0..31
    const int gc = (tid & 7) * 16;     // byte col

    auto load_stage = [&](int ch) {
        uint32_t Ss = sb + (ch & 3) * STG;
        size_t k0 = (size_t)ch * KCH;
#pragma unroll
        for (int p = 0; p < ASZ / 4096; p++) {
            int r = p * 32 + gr;
            CP_ASYNC16(Ss + SWZ(r * 128 + gc),
                       (const char*)(Ag + (size_t)r * KPAD + k0) + gc);
        }
#pragma unroll
        for (int p = 0; p < 2; p++) {
            int r = p * 32 + gr;
            CP_ASYNC16(Ss + ASZ + SWZ(r * 128 + gc),
                       (const char*)(Bg + (k0 + r) * NN) + gc);
        }
    };

    load_stage(0); CP_COMMIT();
    load_stage(1); CP_COMMIT();
    load_stage(2); CP_COMMIT();

    for (int ch = 0; ch < NCHUNK; ch++) {
        CP_WAIT(2);
        __syncthreads();
        if (ch + 3 < NCHUNK) load_stage(ch + 3);
        CP_COMMIT();

        const uint32_t Ab = sb + (ch & 3) * STG;
        const uint32_t Bb = Ab + ASZ;
#pragma unroll
        for (int kk = 0; kk < 4; kk++) {
            uint32_t af[2][4];
#pragma unroll
            for (int mi = 0; mi < 2; mi++) {
                int r = wm * 32 + mi * 16 + (lane & 15);
                int c = kk * 16 + ((lane >> 4) << 3);
                LDSM_X4(af[mi], Ab + SWZ(r * 128 + c * 2));
            }
            uint32_t bf[NTI][2];
#pragma unroll
            for (int ni = 0; ni < NTI; ni++) {
                int r = kk * 16 + (lane & 15);
                int c = wn * (NTI * 8) + ni * 8;
                LDSM_X2T(bf[ni], Bb + SWZ(r * 128 + c * 2));
            }
#pragma unroll
            for (int mi = 0; mi < 2; mi++)
#pragma unroll
                for (int ni = 0; ni < NTI; ni++)
                    MMA16816(acc[mi][ni], af[mi], bf[ni]);
        }
    }

    // ---- epilogue: stage through smem, then coalesced store to L[b][i][h] ----
    __syncthreads();
    float* Cs = (float*)smem;              // [64][NH+1]
    const int g = lane >> 2, tg = lane & 3;
#pragma unroll
    for (int mi = 0; mi < 2; mi++) {
        int h0 = wm * 32 + mi * 16 + g;
#pragma unroll
        for (int ni = 0; ni < NTI; ni++) {
            int ic = wn * (NTI * 8) + ni * 8 + tg * 2;
            Cs[ic * (NH + 1) + h0]           = acc[mi][ni][0];
            Cs[(ic + 1) * (NH + 1) + h0]     = acc[mi][ni][1];
            Cs[ic * (NH + 1) + h0 + 8]       = acc[mi][ni][2];
            Cs[(ic + 1) * (NH + 1) + h0 + 8] = acc[mi][ni][3];
        }
    }
    __syncthreads();
    float* Lp = g_L + ((size_t)b * NN + i0) * NH;
    for (int t = tid; t < 64 * NH; t += 256) {
        int ic = t / NH, h = t - ic * NH;
        Lp[t] = Cs[ic * (NH + 1) + h];
    }
}

// ---------------------------------------------------------------------------
// T1 update: out = relu(L @ Wl + xa * wx);  dest 0 -> g_U, 1/2 -> g_UC halves
// ---------------------------------------------------------------------------
__global__ __launch_bounds__(256) void update1_kernel(
        const float* __restrict__ Wl, const float* __restrict__ wx, int dest) {
    int b = blockIdx.y;
    int i0 = blockIdx.x * 8;
    __shared__ __align__(16) float Ls[8 * 64];
    int tid = threadIdx.x;
    for (int t = tid; t < 512; t += 256)
        Ls[t] = g_L[((size_t)b * NN + i0) * 64 + t];
    __syncthreads();
    int h = tid & 63, iq = tid >> 6;
    float a0 = 0.f, a1 = 0.f;
#pragma unroll 8
    for (int hp = 0; hp < 64; hp++) {
        float wv = Wl[hp * 64 + h];
        a0 = fmaf(Ls[iq * 64 + hp],       wv, a0);
        a1 = fmaf(Ls[(iq + 4) * 64 + hp], wv, a1);
    }
    float wxh = wx[h];
    int i1 = i0 + iq, i2 = i0 + iq + 4;
    float v1 = fmaxf(a0 + g_xa[b * NN + i1] * wxh, 0.f);
    float v2 = fmaxf(a1 + g_xa[b * NN + i2] * wxh, 0.f);
    if (dest == 0) {
        g_U[((size_t)b * NN + i1) * 64 + h] = v1;
        g_U[((size_t)b * NN + i2) * 64 + h] = v2;
    } else {
        int off = (dest == 1) ? 0 : 64;
        g_UC[((size_t)b * NN + i1) * 128 + off + h] = v1;
        g_UC[((size_t)b * NN + i2) * 128 + off + h] = v2;
    }
}

// ---------------------------------------------------------------------------
// dense128: mode 0: g_X2 = g_UC @ W ; mode 1: g_G = relu(g_L @ W + g_X2)
// ---------------------------------------------------------------------------
__global__ __launch_bounds__(256) void dense128_kernel(
        const float* __restrict__ W, int mode) {
    int b = blockIdx.y;
    int i0 = blockIdx.x * 8;
    __shared__ __align__(16) float Ls[8 * 128];
    const float* In = (mode == 0) ? g_UC : g_L;
    int tid = threadIdx.x;
    for (int t = tid; t < 1024; t += 256)
        Ls[t] = In[((size_t)b * NN + i0) * 128 + t];
    __syncthreads();
    int h = tid & 127, iq = tid >> 7;
    float a[4] = {0.f, 0.f, 0.f, 0.f};
#pragma unroll 8
    for (int hp = 0; hp < 128; hp++) {
        float wv = W[hp * 128 + h];
#pragma unroll
        for (int u = 0; u < 4; u++)
            a[u] = fmaf(Ls[(iq + 2 * u) * 128 + hp], wv, a[u]);
    }
#pragma unroll
    for (int u = 0; u < 4; u++) {
        int i = i0 + iq + 2 * u;
        size_t o = ((size_t)b * NN + i) * 128 + h;
        if (mode == 1) g_G[o] = fmaxf(a[u] + g_X2[o], 0.f);
        else           g_X2[o] = a[u];
    }
}

// ---------------------------------------------------------------------------
// Q[b] = sum_{i,h} gamma[b,i,h] * WQ[h]
// ---------------------------------------------------------------------------
__global__ void qreduce_kernel(const float* __restrict__ WQ, float* __restrict__ out) {
    int b = blockIdx.x;
    int tid = threadIdx.x;
    const float* G = g_G + (size_t)b * NN * 128;
    float s = 0.f;
    for (int idx = tid; idx < NN * 128; idx += 256) {
        int h = idx & 127;
        s = fmaf(G[idx], WQ[h], s);
    }
    __shared__ float red[256];
    red[tid] = s; __syncthreads();
    for (int k = 128; k > 0; k >>= 1) {
        if (tid < k) red[tid] += red[tid + k];
        __syncthreads();
    }
    if (tid == 0) out[b] = red[0];
}

// ---------------------------------------------------------------------------
extern "C" void kernel_launch(void* const* d_in, const int* in_sizes, int n_in,
                              void* d_out, int out_size) {
    (void)in_sizes; (void)n_in; (void)out_size;
    const float* x_a_state = (const float*)d_in[0];
    const float* assign_pr = (const float*)d_in[1];
    const float* action    = (const float*)d_in[2];
    const float* edge      = (const float*)d_in[3];
    const float* avail     = (const float*)d_in[4];
    const float* u_a0      = (const float*)d_in[5];
    // d_in[6] = u_b0 : dead in reference
    const float* gamma0    = (const float*)d_in[7];
    const float* W1p       = (const float*)d_in[8];
    const float* W2p       = (const float*)d_in[9];
    const float* W_x_1a    = (const float*)d_in[10];
    const float* W_emb_1a  = (const float*)d_in[11];
    const float* W_l_1a    = (const float*)d_in[12];
    const float* W_x_1b    = (const float*)d_in[13];
    // d_in[14] = W_emb_1b : dead (l_a reuse bug kept)
    const float* W_l_1b    = (const float*)d_in[15];
    const float* W_x_2     = (const float*)d_in[16];
    const float* W_emb_2   = (const float*)d_in[17];
    const float* W_l_2     = (const float*)d_in[18];
    const float* W_Q       = (const float*)d_in[19];
    float* outp = (float*)d_out;

    const int SM64  = 4 * (64 * 128 + 8192);    // 64 KB
    const int SM128 = 4 * (128 * 128 + 8192);   // 96 KB
    cudaFuncSetAttribute(gemm_kernel<64>,
                         cudaFuncAttributeMaxDynamicSharedMemorySize, SM64);
    cudaFuncSetAttribute(gemm_kernel<128>,
                         cudaFuncAttributeMaxDynamicSharedMemorySize, SM128);

    xa_kernel<<<(NB * NN + 255) / 256, 256>>>(x_a_state, assign_pr, action);
    wpow_kernel<<<1, 128>>>(W_emb_1a, W_emb_2);
    presence_kernel<<<dim3(CC, NB), 256>>>(edge, avail, W1p, W2p);

    // ---- T1 ----
    for (int t = 0; t < 5; t++) {
        buildB_kernel<<<dim3(16, NB, 5), 256>>>(t == 0 ? 0 : 1, u_a0, 64, 0);
        gemm_kernel<64><<<dim3(16, NB), 256, SM64>>>();
        if (t < 4) {
            update1_kernel<<<dim3(128, NB), 256>>>(W_l_1a, W_x_1a, 0);
        } else {
            update1_kernel<<<dim3(128, NB), 256>>>(W_l_1a, W_x_1a, 1);
            update1_kernel<<<dim3(128, NB), 256>>>(W_l_1b, W_x_1b, 2);
        }
    }
    dense128_kernel<<<dim3(128, NB), 256>>>(W_x_2, 0);

    // ---- T2 ----
    for (int t = 0; t < 5; t++) {
        buildB_kernel<<<dim3(16, NB, 5), 256>>>(t == 0 ? 0 : 2, gamma0, 128, 1);
        gemm_kernel<128><<<dim3(16, NB), 256, SM128>>>();
        dense128_kernel<<<dim3(128, NB), 256>>>(W_l_2, 1);
    }

    qreduce_kernel<<<NB, 256>>>(W_Q, outp);
}

// round 14
// speedup vs baseline: 6.6538x; 1.2461x over previous
#include <cuda_runtime.h>
#include <cuda_fp16.h>
#include <math.h>
#include <stdint.h>

// ============================================================================
// Model_90168543412725 — graph attention Q network
// B=16, C=1023 cities, N=1024 nodes, H=64, T1=T2=5
//
// sigmoid(d*w), |d*w|<=1 -> Chebyshev-economized deg-5 odd poly
//   sigma(x) ~= 0.5 + c1 x + c3 x^3 + c5 x^5   (max err 2.6e-6)
//   c1=0.24998145, c3=-0.02068091, c5=1.762467e-3
// -> per-iteration GEMM with K = 4*1024 = 4096 (kappa = k*1024 + c; the
// c=1023 Pk rows stay .bss-zero, annihilating garbage Bt there).
//   l[b,i,h] = sum_{k,c} (P[b,i,c] d^pow(k)) * (c_k w_h^pow(k) u[b,c,h])
// Engine: mma.sync.m16n8k16 fp16, fp32 accum, 4-stage cp.async pipeline.
// The iteration update (L@W_l + bias, relu) AND the next iteration's Bt
// build are fused into the GEMM epilogue (L never touches DRAM).
// ============================================================================

#define NB 16
#define CC 1023
#define NN 1024
#define KPAD 4096
#define KCH 64
#define NCHUNK (KPAD / KCH)            // 64
#define PSE ((size_t)NN * NN)          // Pk plane stride (k -> k+1), elements

// ---- scratch (device globals; .bss zero-init — c=1023 rows stay zero) ----
__device__ __align__(16) __half g_Pk [(size_t)NB * KPAD * NN];   // [b][kappa][i]
__device__ __align__(16) __half g_Bt1[(size_t)NB * 64  * KPAD];  // [b][h][kappa]
__device__ __align__(16) __half g_Bt2[(size_t)NB * 128 * KPAD];
__device__ __align__(16) float g_UC[NB * NN * 128];
__device__ __align__(16) float g_X2[NB * NN * 128];
__device__ __align__(16) float g_G [NB * NN * 128];
__device__ float g_xa[NB * NN];
__device__ float g_wp1[4 * 64];        // c_k * w^pow(k), pow={0,1,3,5}
__device__ float g_wp2[4 * 128];

// ---------------------------------------------------------------------------
__device__ __forceinline__ uint32_t s2u(const void* p) {
    uint32_t a;
    asm("{ .reg .u64 t; cvta.to.shared.u64 t, %1; cvt.u32.u64 %0, t; }"
        : "=r"(a) : "l"(p));
    return a;
}
#define SWZ(x) ((x) ^ (((x) >> 3) & 0x70))

#define LDSM_X4(r, addr)                                                      \
    asm volatile("ldmatrix.sync.aligned.m8n8.x4.shared.b16 {%0,%1,%2,%3}, [%4];" \
        : "=r"((r)[0]), "=r"((r)[1]), "=r"((r)[2]), "=r"((r)[3]) : "r"(addr))
#define LDSM_X2T(r, addr)                                                     \
    asm volatile("ldmatrix.sync.aligned.m8n8.x2.trans.shared.b16 {%0,%1}, [%2];" \
        : "=r"((r)[0]), "=r"((r)[1]) : "r"(addr))
#define MMA16816(d, a, bb)                                                    \
    asm volatile(                                                             \
        "mma.sync.aligned.m16n8k16.row.col.f32.f16.f16.f32 "                  \
        "{%0,%1,%2,%3}, {%4,%5,%6,%7}, {%8,%9}, {%0,%1,%2,%3};"               \
        : "+f"((d)[0]), "+f"((d)[1]), "+f"((d)[2]), "+f"((d)[3])              \
        : "r"((a)[0]), "r"((a)[1]), "r"((a)[2]), "r"((a)[3]),                 \
          "r"((bb)[0]), "r"((bb)[1]))
#define CP_ASYNC16(s, g)                                                      \
    asm volatile("cp.async.cg.shared.global [%0], [%1], 16;"                  \
        :: "r"(s), "l"(g) : "memory")
#define CP_COMMIT() asm volatile("cp.async.commit_group;" ::: "memory")
#define CP_WAIT(n)  asm volatile("cp.async.wait_group %0;" :: "n"(n) : "memory")

// ---------------------------------------------------------------------------
// x_a[b,n] = max_r x_a_state[b,r,n] * (assignment_prev + action)[b,r,n]
// ---------------------------------------------------------------------------
__global__ void xa_kernel(const float* __restrict__ xs,
                          const float* __restrict__ ap,
                          const float* __restrict__ act) {
    int idx = blockIdx.x * 256 + threadIdx.x;
    if (idx >= NB * NN) return;
    int b = idx >> 10, n = idx & 1023;
    float mx = -3.4e38f;
#pragma unroll
    for (int r = 0; r < 8; r++) {
        int o = (b * 8 + r) * NN + n;
        mx = fmaxf(mx, xs[o] * (ap[o] + act[o]));
    }
    g_xa[idx] = mx;
}

// ---------------------------------------------------------------------------
// wp[k][h] = c_k * w_h^pow(k),  pow = {0,1,3,5}, Chebyshev-economized
// ---------------------------------------------------------------------------
__global__ void wpow_kernel(const float* __restrict__ w1a,
                            const float* __restrict__ w2) {
    const float c0 = 0.5f, c1 = 0.24998145f, c3 = -0.02068091f,
                c5 = 1.762467e-3f;
    int h = threadIdx.x;
    if (h < 64) {
        float w = w1a[h]; float ww = w * w;
        float w3 = w * ww, w5 = w3 * ww;
        g_wp1[0*64+h] = c0;     g_wp1[1*64+h] = c1*w;
        g_wp1[2*64+h] = c3*w3;  g_wp1[3*64+h] = c5*w5;
    }
    if (h < 128) {
        float w = w2[h]; float ww = w * w;
        float w3 = w * ww, w5 = w3 * ww;
        g_wp2[0*128+h] = c0;    g_wp2[1*128+h] = c1*w;
        g_wp2[2*128+h] = c3*w3; g_wp2[3*128+h] = c5*w5;
    }
}

// ---------------------------------------------------------------------------
// Presence attention + Pk build. One block per (b,c).
// MLP h1/h2 in packed half2 (HFMA2), softmax in fp32.
// Pk[b][k*1024+c][n] = softmax_n(logit)[n] * d(n)^pow(k), pow={0,1,3,5}
// ---------------------------------------------------------------------------
__global__ __launch_bounds__(256) void presence_kernel(
        const float* __restrict__ edge, const float* __restrict__ avail,
        const float* __restrict__ W1, const float* __restrict__ W2) {
    const int c = blockIdx.x;
    const int b = blockIdx.y;
    __shared__ __align__(16) uint4 wpk[32];   // [j] = {wx2, wy2, wz2, w22}
    __shared__ float lbuf[1024];
    __shared__ float dbuf[1024];
    __shared__ float red[256];
    int tid = threadIdx.x;
    if (tid < 32) {
        int j = tid;
        __half2 wx = __floats2half2_rn(W1[2*j],       W1[2*j + 1]);
        __half2 wy = __floats2half2_rn(W1[64 + 2*j],  W1[64 + 2*j + 1]);
        __half2 wz = __floats2half2_rn(W1[128 + 2*j], W1[128 + 2*j + 1]);
        __half2 w2 = __floats2half2_rn(W2[2*j],       W2[2*j + 1]);
        uint4 v;
        v.x = *(uint32_t*)&wx; v.y = *(uint32_t*)&wy;
        v.z = *(uint32_t*)&wz; v.w = *(uint32_t*)&w2;
        wpk[j] = v;
    }
    __syncthreads();

    float e0s[4];
    __half2 E0[4], E1[4], E2[4], S[4];
    const __half2 zero2 = __float2half2_rn(0.f);
#pragma unroll
    for (int q = 0; q < 4; q++) {
        int n = tid + q * 256;
        size_t base = ((size_t)(b * CC + c) * NN + n) * 3;
        float e0 = edge[base], e1 = edge[base + 1], e2 = edge[base + 2];
        e0s[q] = e0;
        E0[q] = __float2half2_rn(e0);
        E1[q] = __float2half2_rn(e1);
        E2[q] = __float2half2_rn(e2);
        S[q] = zero2;
    }
#pragma unroll 8
    for (int j = 0; j < 32; j++) {
        uint4 v = wpk[j];
        __half2 wx = *(__half2*)&v.x, wy = *(__half2*)&v.y;
        __half2 wz = *(__half2*)&v.z, w2 = *(__half2*)&v.w;
#pragma unroll
        for (int q = 0; q < 4; q++) {
            __half2 t = __hfma2(E0[q], wx, __hfma2(E1[q], wy, __hmul2(E2[q], wz)));
            t = __hmax2(t, zero2);
            S[q] = __hfma2(t, w2, S[q]);
        }
    }
#pragma unroll
    for (int q = 0; q < 4; q++) {
        int n = tid + q * 256;
        float h2 = fmaxf(__low2float(S[q]) + __high2float(S[q]), 0.f);
        float m = (n == c ? 0.f : 1.f) * avail[b * NN + n];
        lbuf[n] = h2 * m - (1.f - m) * 1e10f;
        dbuf[n] = e0s[q];
    }
    __syncthreads();

    float mx = -3.4e38f;
    for (int n = tid; n < NN; n += 256) mx = fmaxf(mx, lbuf[n]);
    red[tid] = mx; __syncthreads();
    for (int k = 128; k > 0; k >>= 1) {
        if (tid < k) red[tid] = fmaxf(red[tid], red[tid + k]);
        __syncthreads();
    }
    mx = red[0];

    float sm = 0.f;
    for (int n = tid; n < NN; n += 256) {
        float e = __expf(lbuf[n] - mx);
        lbuf[n] = e; sm += e;
    }
    __syncthreads();
    red[tid] = sm; __syncthreads();
    for (int k = 128; k > 0; k >>= 1) {
        if (tid < k) red[tid] += red[tid + k];
        __syncthreads();
    }
    float inv = 1.f / red[0];

    for (int n = tid; n < NN; n += 256) {
        float p = lbuf[n] * inv;
        float d = dbuf[n];
        float d2 = d * d;
        size_t i0 = ((size_t)b * KPAD + c) * NN + n;   // kappa = k*1024 + c
        g_Pk[i0]           = __float2half(p);          // d^0
        float q = p * d;  g_Pk[i0 + PSE]     = __float2half(q);   // d^1
        q *= d2;          g_Pk[i0 + 2 * PSE] = __float2half(q);   // d^3
        q *= d2;          g_Pk[i0 + 3 * PSE] = __float2half(q);   // d^5
    }
}

// ---------------------------------------------------------------------------
// buildB (loop entry only): Bt[b][h][k*1024+c] = wp[k][h] * U0[b][c][h]
// grid (16 c-tiles, NB, 4 k). c=1023 entries garbage -> killed by zero Pk rows.
// ---------------------------------------------------------------------------
__global__ __launch_bounds__(256) void buildB_kernel(const float* __restrict__ U,
                                                     int NH, int phase) {
    int b = blockIdx.y, c0 = blockIdx.x * 64, k = blockIdx.z;
    __shared__ float Us[64 * 129];
    const int stride = NH + 1;
    const float* wp = (NH == 64) ? g_wp1 : g_wp2;
    __half* Bt = phase ? g_Bt2 : g_Bt1;
    int tid = threadIdx.x;
    for (int idx = tid; idx < 64 * NH; idx += 256) {
        int cl = idx / NH, h = idx - cl * NH;
        Us[cl * stride + h] = U[((size_t)b * NN + c0 + cl) * NH + h];
    }
    __syncthreads();
    int w = tid >> 5, l = tid & 31;
    int HR = (NH == 64) ? 64 : 128;
    for (int h = w; h < NH; h += 8) {
        float s = wp[k * NH + h];
        __half2 v = __floats2half2_rn(s * Us[(2 * l) * stride + h],
                                      s * Us[(2 * l + 1) * stride + h]);
        *(__half2*)(Bt + ((size_t)b * HR + h) * KPAD + k * 1024 + c0 + 2 * l) = v;
    }
}

// ---------------------------------------------------------------------------
// fp16 GEMM + fused iteration update + Bt rebuild.
//   L[i][h] = sum_kappa Bt[h][kappa] * Pk[kappa][i]   (tensor cores)
// epilogue (NH=64, T1):  u = relu(L@Wl_a + xa*wx_a)
//    non-final: Bt1[h][k*1024+(i0+i)] = wp1[k][h]*u[i][h]
//    final:     UC[:, :64] = u_a ; UC[:, 64:] = relu(L@Wl_b + xa*wx_b)
// epilogue (NH=128, T2): g = relu(L@Wl + X2)
//    non-final: Bt2[...] = wp2[k][h]*g ;  final: g_G = g
// grid (16 i-tiles, NB), 256 threads / 8 warps.
// ---------------------------------------------------------------------------
template<int NH>
__global__ void __launch_bounds__(256) gemm_kernel(
        const float* __restrict__ Wl, const float* __restrict__ wxa,
        const float* __restrict__ Wlb, const float* __restrict__ wxb,
        int is_final) {
    constexpr int ASZ = NH * 128;          // bytes per A stage
    constexpr int BSZ = 64 * 128;          // 8 KB per B stage
    constexpr int STG = ASZ + BSZ;
    constexpr int WN  = (NH == 128) ? 2 : 4;
    constexpr int NTI = (NH == 128) ? 4 : 2;
    constexpr int CSP = NH + 2;            // Cs row stride (even)
    extern __shared__ __align__(128) char smem[];

    const int b = blockIdx.y;
    const int i0 = blockIdx.x * 64;
    const __half* Ag = (NH == 64 ? g_Bt1 : g_Bt2) + (size_t)b * NH * KPAD;
    const __half* Bg = g_Pk + (size_t)b * KPAD * NN + i0;

    const int tid = threadIdx.x, lane = tid & 31, wid = tid >> 5;
    const int wm = wid / WN, wn = wid % WN;
    const uint32_t sb = s2u(smem);

    float acc[2][NTI][4];
#pragma unroll
    for (int mi = 0; mi < 2; mi++)
#pragma unroll
        for (int ni = 0; ni < NTI; ni++)
#pragma unroll
            for (int q = 0; q < 4; q++) acc[mi][ni][q] = 0.f;

    const int gr = tid >> 3;           // 0..31
    const int gc = (tid & 7) * 16;     // byte col

    auto load_stage = [&](int ch) {
        uint32_t Ss = sb + (ch & 3) * STG;
        size_t k0 = (size_t)ch * KCH;
#pragma unroll
        for (int p = 0; p < ASZ / 4096; p++) {
            int r = p * 32 + gr;
            CP_ASYNC16(Ss + SWZ(r * 128 + gc),
                       (const char*)(Ag + (size_t)r * KPAD + k0) + gc);
        }
#pragma unroll
        for (int p = 0; p < 2; p++) {
            int r = p * 32 + gr;
            CP_ASYNC16(Ss + ASZ + SWZ(r * 128 + gc),
                       (const char*)(Bg + (k0 + r) * NN) + gc);
        }
    };

    load_stage(0); CP_COMMIT();
    load_stage(1); CP_COMMIT();
    load_stage(2); CP_COMMIT();

    for (int ch = 0; ch < NCHUNK; ch++) {
        CP_WAIT(2);
        __syncthreads();
        if (ch + 3 < NCHUNK) load_stage(ch + 3);
        CP_COMMIT();

        const uint32_t Ab = sb + (ch & 3) * STG;
        const uint32_t Bb = Ab + ASZ;
#pragma unroll
        for (int kk = 0; kk < 4; kk++) {
            uint32_t af[2][4];
#pragma unroll
            for (int mi = 0; mi < 2; mi++) {
                int r = wm * 32 + mi * 16 + (lane & 15);
                int c = kk * 16 + ((lane >> 4) << 3);
                LDSM_X4(af[mi], Ab + SWZ(r * 128 + c * 2));
            }
            uint32_t bf[NTI][2];
#pragma unroll
            for (int ni = 0; ni < NTI; ni++) {
                int r = kk * 16 + (lane & 15);
                int c = wn * (NTI * 8) + ni * 8;
                LDSM_X2T(bf[ni], Bb + SWZ(r * 128 + c * 2));
            }
#pragma unroll
            for (int mi = 0; mi < 2; mi++)
#pragma unroll
                for (int ni = 0; ni < NTI; ni++)
                    MMA16816(acc[mi][ni], af[mi], bf[ni]);
        }
    }

    // ---- stage L tile into smem (Cs[i][h], padded stride CSP) ----
    CP_WAIT(0);
    __syncthreads();
    float* Cs = (float*)smem;
    const int g = lane >> 2, tg = lane & 3;
#pragma unroll
    for (int mi = 0; mi < 2; mi++) {
        int h0 = wm * 32 + mi * 16 + g;
#pragma unroll
        for (int ni = 0; ni < NTI; ni++) {
            int ic = wn * (NTI * 8) + ni * 8 + tg * 2;
            Cs[ic * CSP + h0]           = acc[mi][ni][0];
            Cs[(ic + 1) * CSP + h0]     = acc[mi][ni][1];
            Cs[ic * CSP + h0 + 8]       = acc[mi][ni][2];
            Cs[(ic + 1) * CSP + h0 + 8] = acc[mi][ni][3];
        }
    }
    __syncthreads();

    if (NH == 64) {
        const int h = tid & 63, iq = tid >> 6;    // iq 0..3, 16 i's per thread
        float vals[16];
        // ---- u_a = relu(L @ Wl + xa*wxa) ----
#pragma unroll
        for (int u = 0; u < 16; u++) vals[u] = 0.f;
#pragma unroll 8
        for (int hp = 0; hp < 64; hp++) {
            float wv = Wl[hp * 64 + h];
#pragma unroll
            for (int u = 0; u < 16; u++)
                vals[u] = fmaf(Cs[(iq + 4 * u) * CSP + hp], wv, vals[u]);
        }
        float wxh = wxa[h];
#pragma unroll
        for (int u = 0; u < 16; u++)
            vals[u] = fmaxf(vals[u] + g_xa[b * NN + i0 + iq + 4 * u] * wxh, 0.f);

        if (!is_final) {
            float* U2 = (float*)(smem + 20480);   // [64][65]
#pragma unroll
            for (int u = 0; u < 16; u++)
                U2[h * 65 + iq + 4 * u] = vals[u];
            __syncthreads();
            __half* Btp = g_Bt1 + (size_t)b * 64 * KPAD;
            for (int row = wid; row < 256; row += 8) {
                int hh = row & 63, k = row >> 6;
                float s = g_wp1[k * 64 + hh];
                float ux = U2[hh * 65 + 2 * lane];
                float uy = U2[hh * 65 + 2 * lane + 1];
                *(__half2*)(Btp + (size_t)hh * KPAD + k * 1024 + i0 + 2 * lane) =
                    __floats2half2_rn(s * ux, s * uy);
            }
        } else {
            float* UCp = g_UC + ((size_t)b * NN + i0) * 128;
#pragma unroll
            for (int u = 0; u < 16; u++)
                UCp[(iq + 4 * u) * 128 + h] = vals[u];
            // ---- u_b = relu(L @ Wlb + xa*wxb)  (same L, per reference bug) ----
#pragma unroll
            for (int u = 0; u < 16; u++) vals[u] = 0.f;
#pragma unroll 8
            for (int hp = 0; hp < 64; hp++) {
                float wv = Wlb[hp * 64 + h];
#pragma unroll
                for (int u = 0; u < 16; u++)
                    vals[u] = fmaf(Cs[(iq + 4 * u) * CSP + hp], wv, vals[u]);
            }
            float wxbh = wxb[h];
#pragma unroll
            for (int u = 0; u < 16; u++) {
                float v = fmaxf(vals[u] + g_xa[b * NN + i0 + iq + 4 * u] * wxbh, 0.f);
                UCp[(iq + 4 * u) * 128 + 64 + h] = v;
            }
        }
    } else {
        const int h = tid & 127, iq = tid >> 7;   // iq 0..1, 32 i's per thread
        const float* X2p = g_X2 + ((size_t)b * NN + i0) * 128;
        float* U2 = (float*)(smem + 36864);        // [128][65]
        float* Gp = g_G + ((size_t)b * NN + i0) * 128;
        // two passes of 16 i's to bound register pressure
#pragma unroll
        for (int half = 0; half < 2; half++) {
            float vals[16];
#pragma unroll
            for (int u = 0; u < 16; u++) vals[u] = 0.f;
#pragma unroll 4
            for (int hp = 0; hp < 128; hp++) {
                float wv = Wl[hp * 128 + h];
#pragma unroll
                for (int u = 0; u < 16; u++) {
                    int i = iq + 2 * (u + 16 * half);
                    vals[u] = fmaf(Cs[i * CSP + hp], wv, vals[u]);
                }
            }
#pragma unroll
            for (int u = 0; u < 16; u++) {
                int i = iq + 2 * (u + 16 * half);
                vals[u] = fmaxf(vals[u] + X2p[i * 128 + h], 0.f);
                if (is_final) Gp[i * 128 + h] = vals[u];
                else          U2[h * 65 + i] = vals[u];
            }
        }
        if (!is_final) {
            __syncthreads();
            __half* Btp = g_Bt2 + (size_t)b * 128 * KPAD;
            for (int row = wid; row < 512; row += 8) {
                int hh = row & 127, k = row >> 7;
                float s = g_wp2[k * 128 + hh];
                float ux = U2[hh * 65 + 2 * lane];
                float uy = U2[hh * 65 + 2 * lane + 1];
                *(__half2*)(Btp + (size_t)hh * KPAD + k * 1024 + i0 + 2 * lane) =
                    __floats2half2_rn(s * ux, s * uy);
            }
        }
    }
}

// ---------------------------------------------------------------------------
// x2: g_X2 = g_UC @ W_x_2  (no bias/relu)
// ---------------------------------------------------------------------------
__global__ __launch_bounds__(256) void x2_kernel(const float* __restrict__ W) {
    int b = blockIdx.y;
    int i0 = blockIdx.x * 8;
    __shared__ __align__(16) float Ls[8 * 128];
    int tid = threadIdx.x;
    for (int t = tid; t < 1024; t += 256)
        Ls[t] = g_UC[((size_t)b * NN + i0) * 128 + t];
    __syncthreads();
    int h = tid & 127, iq = tid >> 7;
    float a[4] = {0.f, 0.f, 0.f, 0.f};
#pragma unroll 8
    for (int hp = 0; hp < 128; hp++) {
        float wv = W[hp * 128 + h];
#pragma unroll
        for (int u = 0; u < 4; u++)
            a[u] = fmaf(Ls[(iq + 2 * u) * 128 + hp], wv, a[u]);
    }
#pragma unroll
    for (int u = 0; u < 4; u++) {
        int i = i0 + iq + 2 * u;
        g_X2[((size_t)b * NN + i) * 128 + h] = a[u];
    }
}

// ---------------------------------------------------------------------------
// Q[b] = sum_{i,h} gamma[b,i,h] * WQ[h]
// ---------------------------------------------------------------------------
__global__ void qreduce_kernel(const float* __restrict__ WQ, float* __restrict__ out) {
    int b = blockIdx.x;
    int tid = threadIdx.x;
    const float* G = g_G + (size_t)b * NN * 128;
    float s = 0.f;
    for (int idx = tid; idx < NN * 128; idx += 256) {
        int h = idx & 127;
        s = fmaf(G[idx], WQ[h], s);
    }
    __shared__ float red[256];
    red[tid] = s; __syncthreads();
    for (int k = 128; k > 0; k >>= 1) {
        if (tid < k) red[tid] += red[tid + k];
        __syncthreads();
    }
    if (tid == 0) out[b] = red[0];
}

// ---------------------------------------------------------------------------
extern "C" void kernel_launch(void* const* d_in, const int* in_sizes, int n_in,
                              void* d_out, int out_size) {
    (void)in_sizes; (void)n_in; (void)out_size;
    const float* x_a_state = (const float*)d_in[0];
    const float* assign_pr = (const float*)d_in[1];
    const float* action    = (const float*)d_in[2];
    const float* edge      = (const float*)d_in[3];
    const float* avail     = (const float*)d_in[4];
    const float* u_a0      = (const float*)d_in[5];
    // d_in[6] = u_b0 : dead in reference
    const float* gamma0    = (const float*)d_in[7];
    const float* W1p       = (const float*)d_in[8];
    const float* W2p       = (const float*)d_in[9];
    const float* W_x_1a    = (const float*)d_in[10];
    const float* W_emb_1a  = (const float*)d_in[11];
    const float* W_l_1a    = (const float*)d_in[12];
    const float* W_x_1b    = (const float*)d_in[13];
    // d_in[14] = W_emb_1b : dead (l_a reuse bug kept)
    const float* W_l_1b    = (const float*)d_in[15];
    const float* W_x_2     = (const float*)d_in[16];
    const float* W_emb_2   = (const float*)d_in[17];
    const float* W_l_2     = (const float*)d_in[18];
    const float* W_Q       = (const float*)d_in[19];
    float* outp = (float*)d_out;

    const int SM64  = 4 * (64 * 128 + 8192);    // 64 KB
    const int SM128 = 4 * (128 * 128 + 8192);   // 96 KB
    cudaFuncSetAttribute(gemm_kernel<64>,
                         cudaFuncAttributeMaxDynamicSharedMemorySize, SM64);
    cudaFuncSetAttribute(gemm_kernel<128>,
                         cudaFuncAttributeMaxDynamicSharedMemorySize, SM128);

    xa_kernel<<<(NB * NN + 255) / 256, 256>>>(x_a_state, assign_pr, action);
    wpow_kernel<<<1, 128>>>(W_emb_1a, W_emb_2);
    presence_kernel<<<dim3(CC, NB), 256>>>(edge, avail, W1p, W2p);

    // ---- T1 (fused update+Bt in GEMM epilogue) ----
    buildB_kernel<<<dim3(16, NB, 4), 256>>>(u_a0, 64, 0);
    for (int t = 0; t < 5; t++)
        gemm_kernel<64><<<dim3(16, NB), 256, SM64>>>(
            W_l_1a, W_x_1a, W_l_1b, W_x_1b, t == 4);

    x2_kernel<<<dim3(128, NB), 256>>>(W_x_2);

    // ---- T2 ----
    buildB_kernel<<<dim3(16, NB, 4), 256>>>(gamma0, 128, 1);
    for (int t = 0; t < 5; t++)
        gemm_kernel<128><<<dim3(16, NB), 256, SM128>>>(
            W_l_2, nullptr, nullptr, nullptr, t == 4);

    qreduce_kernel<<<NB, 256>>>(W_Q, outp);
}